// round 6
// baseline (speedup 1.0000x reference)
#include <cuda_runtime.h>
#include <math.h>
#include <stdint.h>

// ---------------------------------------------------------------------------
// Dims: D=512, K=8, L=64, Q=4096, C=4096
//   Tk[k][c][d] = sum_i class[c,i]*M[i,d,k]       (3xTF32 mma GEMM, scatter)
//   other[q,c]  = b + sum_k w_k*relu(sum_d qtf[q,d]*Tk[k][c][d])  (tf32 mma)
//   scores      = softmax_rows(other)
//   qf          = scores @ class + query           (3xTF32 mma, split-K=4)
//   out         = tanh(qf @ hash_w^T + hash_b)     (SIMT GEMM)
// Target sm_103 (no 'a'): mma.sync/cp.async only, no tcgen05.
// ---------------------------------------------------------------------------

__device__ float g_T[(size_t)8 * 4096 * 512];    // 64 MB: Tk[k][c][d]
__device__ float g_other[(size_t)4096 * 4096];   // 64 MB
__device__ float g_qf[(size_t)4096 * 512];       // 8 MB
__device__ float g_qtf[(size_t)4096 * 512];      // 8 MB tf32-rounded query
__device__ float g_hwT[512 * 64];
__device__ float g_MT_hi[(size_t)4096 * 512];    // M^T  [jk][i] hi
__device__ float g_MT_lo[(size_t)4096 * 512];    //               lo
__device__ float g_clT_hi[(size_t)512 * 4096];   // class^T [d][c] hi
__device__ float g_clT_lo[(size_t)512 * 4096];   //               lo
__device__ float g_qfp[(size_t)4 * 4096 * 512];  // 32 MB split-K partials

// ------------------------------ helpers -----------------------------------
__device__ __forceinline__ uint32_t smem_u32(const void* p) {
    uint32_t a;
    asm("{ .reg .u64 t; cvta.to.shared.u64 t, %1; cvt.u32.u64 %0, t; }" : "=r"(a) : "l"(p));
    return a;
}
__device__ __forceinline__ float tf32r(float x) {
    unsigned u;
    asm("cvt.rna.tf32.f32 %0, %1;" : "=r"(u) : "f"(x));
    return __uint_as_float(u);
}
__device__ __forceinline__ void mma_tf32(float* c, const float* a, const float* b) {
    asm volatile(
        "mma.sync.aligned.m16n8k8.row.col.f32.tf32.tf32.f32 "
        "{%0,%1,%2,%3}, {%4,%5,%6,%7}, {%8,%9}, {%0,%1,%2,%3};"
        : "+f"(c[0]), "+f"(c[1]), "+f"(c[2]), "+f"(c[3])
        : "r"(__float_as_uint(a[0])), "r"(__float_as_uint(a[1])),
          "r"(__float_as_uint(a[2])), "r"(__float_as_uint(a[3])),
          "r"(__float_as_uint(b[0])), "r"(__float_as_uint(b[1])));
}

// ---------------------------------------------------------------------------
// Generic tiled fp32 SIMT GEMM (kept for stage 5). EPI 2: tanh(acc + X[c]).
// ---------------------------------------------------------------------------
template <int BM, int BN, int BK, int TM, int TN, int EPI>
__global__ void __launch_bounds__((BM / TM) * (BN / TN), 2)
gemm_f32(const float* __restrict__ A, const float* __restrict__ B,
         const float* __restrict__ X, float* __restrict__ out,
         int M, int N, int K)
{
    constexpr int THREADS = (BM / TM) * (BN / TN);
    __shared__ float As[BK][BM + 4];
    __shared__ float Bs[BK][BN + 4];

    const int bm = blockIdx.y * BM;
    const int bn = blockIdx.x * BN;
    const int tid = threadIdx.x;
    const int tcol = tid % (BN / TN);
    const int trow = tid / (BN / TN);

    float acc[TM][TN];
#pragma unroll
    for (int i = 0; i < TM; i++)
#pragma unroll
        for (int j = 0; j < TN; j++) acc[i][j] = 0.0f;

    for (int k0 = 0; k0 < K; k0 += BK) {
#pragma unroll
        for (int it = 0; it < (BM * BK / 4) / THREADS; it++) {
            int i = tid + it * THREADS;
            int r = i / (BK / 4);
            int c4 = (i % (BK / 4)) * 4;
            float4 v = *(const float4*)(A + (size_t)(bm + r) * K + k0 + c4);
            As[c4 + 0][r] = v.x; As[c4 + 1][r] = v.y;
            As[c4 + 2][r] = v.z; As[c4 + 3][r] = v.w;
        }
#pragma unroll
        for (int it = 0; it < (BK * BN / 4) / THREADS; it++) {
            int i = tid + it * THREADS;
            int r = i / (BN / 4);
            int c4 = (i % (BN / 4)) * 4;
            *(float4*)&Bs[r][c4] = *(const float4*)(B + (size_t)(k0 + r) * N + bn + c4);
        }
        __syncthreads();

#pragma unroll
        for (int kk = 0; kk < BK; kk++) {
            float af[TM], bf[TN];
#pragma unroll
            for (int i = 0; i < TM; i += 4) {
                float4 v = *(const float4*)&As[kk][trow * TM + i];
                af[i] = v.x; af[i + 1] = v.y; af[i + 2] = v.z; af[i + 3] = v.w;
            }
#pragma unroll
            for (int j = 0; j < TN; j += 4) {
                float4 v = *(const float4*)&Bs[kk][tcol * TN + j];
                bf[j] = v.x; bf[j + 1] = v.y; bf[j + 2] = v.z; bf[j + 3] = v.w;
            }
#pragma unroll
            for (int i = 0; i < TM; i++)
#pragma unroll
                for (int j = 0; j < TN; j++)
                    acc[i][j] = fmaf(af[i], bf[j], acc[i][j]);
        }
        __syncthreads();
    }

#pragma unroll
    for (int i = 0; i < TM; i++) {
        int r = bm + trow * TM + i;
#pragma unroll
        for (int j = 0; j < TN; j++) {
            int c = bn + tcol * TN + j;
            float v = acc[i][j];
            if (EPI == 2) v = tanhf(v + X[c]);
            out[(size_t)r * N + c] = v;
        }
    }
}

// ---------------------------------------------------------------------------
// 3xTF32 mma GEMM: out = A[M,Kr] @ Bt[N,Kr]^T, near-fp32 accuracy.
// A fp32 (hi/lo split in registers); Bt pre-split into Bhi/Blo.
// CTA 128m x 128n, 8 warps (2x4), warp tile 64x32, chunk=32, double buffer.
// kseg: reduction length per z-slice; kstart = z*kseg.
//   EPI 0: scatter tf32r(v) to Tk layout ((c&7)<<21) + r*512 + (c>>3)
//   EPI 1: store partial to out + z*4096*512 at [r*512+c]
// ---------------------------------------------------------------------------
#define G3_PAD 36
#define G3_TILE (128 * G3_PAD)
#define G3_SMEM (6 * G3_TILE * 4)   // 110592 B

template <int EPI>
__device__ __forceinline__ void g3_load(float* As, float* Bh, float* Bl,
                                        const float* __restrict__ A,
                                        const float* __restrict__ Bhi,
                                        const float* __restrict__ Blo,
                                        int m0, int n0, int lda, int ldb,
                                        int kofs, int tid, int buf)
{
    const int row = tid >> 3;
    const int f4 = (tid & 7) * 4;
    uint32_t da = smem_u32(As + buf * G3_TILE + row * G3_PAD + f4);
    uint32_t dh = smem_u32(Bh + buf * G3_TILE + row * G3_PAD + f4);
    uint32_t dl = smem_u32(Bl + buf * G3_TILE + row * G3_PAD + f4);
    const float* ga = A + (size_t)(m0 + row) * lda + kofs + f4;
    const float* gh = Bhi + (size_t)(n0 + row) * ldb + kofs + f4;
    const float* gl = Blo + (size_t)(n0 + row) * ldb + kofs + f4;
#pragma unroll
    for (int i = 0; i < 4; i++) {
        asm volatile("cp.async.cg.shared.global [%0], [%1], 16;"
                     :: "r"(da + i * 32 * G3_PAD * 4), "l"(ga + (size_t)i * 32 * lda));
        asm volatile("cp.async.cg.shared.global [%0], [%1], 16;"
                     :: "r"(dh + i * 32 * G3_PAD * 4), "l"(gh + (size_t)i * 32 * ldb));
        asm volatile("cp.async.cg.shared.global [%0], [%1], 16;"
                     :: "r"(dl + i * 32 * G3_PAD * 4), "l"(gl + (size_t)i * 32 * ldb));
    }
    asm volatile("cp.async.commit_group;" ::: "memory");
}

template <int EPI>
__global__ void __launch_bounds__(256, 1)
gemm3x(const float* __restrict__ A,
       const float* __restrict__ Bhi, const float* __restrict__ Blo,
       float* __restrict__ out, int lda, int ldb, int kseg)
{
    extern __shared__ float smf[];
    float* As = smf;
    float* Bh = smf + 2 * G3_TILE;
    float* Bl = smf + 4 * G3_TILE;

    const int tid = threadIdx.x;
    const int lane = tid & 31;
    const int wid = tid >> 5;
    const int wm = wid >> 2;
    const int wn = wid & 3;
    const int m0 = blockIdx.y * 128;
    const int n0 = blockIdx.x * 128;
    const int kstart = blockIdx.z * kseg;
    const int nchunks = kseg / 32;

    const int lq = lane >> 2;
    const int ld = lane & 3;

    float macc[4][4][4];
#pragma unroll
    for (int mi = 0; mi < 4; mi++)
#pragma unroll
        for (int ni = 0; ni < 4; ni++)
#pragma unroll
            for (int r = 0; r < 4; r++) macc[mi][ni][r] = 0.0f;

    g3_load<EPI>(As, Bh, Bl, A, Bhi, Blo, m0, n0, lda, ldb, kstart, tid, 0);

    for (int t = 0; t < nchunks; t++) {
        const int buf = t & 1;
        if (t < nchunks - 1) {
            g3_load<EPI>(As, Bh, Bl, A, Bhi, Blo, m0, n0, lda, ldb,
                         kstart + (t + 1) * 32, tid, buf ^ 1);
            asm volatile("cp.async.wait_group 1;" ::: "memory");
        } else {
            asm volatile("cp.async.wait_group 0;" ::: "memory");
        }
        __syncthreads();

        const float* pa = As + buf * G3_TILE;
        const float* ph = Bh + buf * G3_TILE;
        const float* pl = Bl + buf * G3_TILE;
#pragma unroll
        for (int d8 = 0; d8 < 4; d8++) {
            float ahi[4][4], alo[4][4];
#pragma unroll
            for (int mi = 0; mi < 4; mi++) {
                const float* p = pa + (wm * 64 + mi * 16 + lq) * G3_PAD + d8 * 8 + ld;
                float a0 = p[0], a1 = p[8 * G3_PAD], a2 = p[4], a3 = p[8 * G3_PAD + 4];
                ahi[mi][0] = tf32r(a0); alo[mi][0] = tf32r(a0 - ahi[mi][0]);
                ahi[mi][1] = tf32r(a1); alo[mi][1] = tf32r(a1 - ahi[mi][1]);
                ahi[mi][2] = tf32r(a2); alo[mi][2] = tf32r(a2 - ahi[mi][2]);
                ahi[mi][3] = tf32r(a3); alo[mi][3] = tf32r(a3 - ahi[mi][3]);
            }
            float bh[4][2], bl[4][2];
#pragma unroll
            for (int ni = 0; ni < 4; ni++) {
                const float* p = ph + (wn * 32 + ni * 8 + lq) * G3_PAD + d8 * 8 + ld;
                bh[ni][0] = p[0]; bh[ni][1] = p[4];
                const float* p2 = pl + (wn * 32 + ni * 8 + lq) * G3_PAD + d8 * 8 + ld;
                bl[ni][0] = p2[0]; bl[ni][1] = p2[4];
            }
#pragma unroll
            for (int mi = 0; mi < 4; mi++)
#pragma unroll
                for (int ni = 0; ni < 4; ni++) {
                    mma_tf32(macc[mi][ni], ahi[mi], bh[ni]);
                    mma_tf32(macc[mi][ni], alo[mi], bh[ni]);
                    mma_tf32(macc[mi][ni], ahi[mi], bl[ni]);
                }
        }
        __syncthreads();
    }

    // epilogue
    if (EPI == 0) {
#pragma unroll
        for (int mi = 0; mi < 4; mi++) {
            const int r = m0 + wm * 64 + mi * 16 + lq;
#pragma unroll
            for (int ni = 0; ni < 4; ni++) {
                const int c = n0 + wn * 32 + ni * 8 + 2 * ld;
#pragma unroll
                for (int rr = 0; rr < 4; rr++) {
                    int row = r + (rr >> 1) * 8;
                    int col = c + (rr & 1);
                    size_t idx = ((size_t)(col & 7) << 21) + (size_t)row * 512 + (size_t)(col >> 3);
                    out[idx] = tf32r(macc[mi][ni][rr]);
                }
            }
        }
    } else {
        float* ob = out + (size_t)blockIdx.z * 4096 * 512;
#pragma unroll
        for (int mi = 0; mi < 4; mi++) {
            const int r = m0 + wm * 64 + mi * 16 + lq;
#pragma unroll
            for (int ni = 0; ni < 4; ni++) {
                const int c = n0 + wn * 32 + ni * 8 + 2 * ld;
                *(float2*)(ob + (size_t)r * 512 + c) =
                    make_float2(macc[mi][ni][0], macc[mi][ni][1]);
                *(float2*)(ob + (size_t)(r + 8) * 512 + c) =
                    make_float2(macc[mi][ni][2], macc[mi][ni][3]);
            }
        }
    }
}

// ---------------------------------------------------------------------------
// Stage 2: mma.sync tf32 fused bilinear + relu + score. (unchanged from R4)
// ---------------------------------------------------------------------------
#define S2_ROWPAD 36
#define S2_TILE (128 * S2_ROWPAD)
#define S2_SMEM (4 * S2_TILE * 4)

__device__ __forceinline__ void s2_load(float* As, float* Bs,
                                        const float* __restrict__ qtf,
                                        const float* __restrict__ Tk,
                                        int q0, int c0, int tid, int k, int t, int buf)
{
    const int row = tid >> 3;
    const int f4 = (tid & 7) * 4;
    const float* ga = qtf + (size_t)(q0 + row) * 512 + t * 32 + f4;
    const float* gb = Tk + ((size_t)k << 21) + (size_t)(c0 + row) * 512 + t * 32 + f4;
    uint32_t da = smem_u32(As + buf * S2_TILE + row * S2_ROWPAD + f4);
    uint32_t db = smem_u32(Bs + buf * S2_TILE + row * S2_ROWPAD + f4);
#pragma unroll
    for (int i = 0; i < 4; i++) {
        asm volatile("cp.async.cg.shared.global [%0], [%1], 16;"
                     :: "r"(da + i * 32 * S2_ROWPAD * 4), "l"(ga + (size_t)i * 32 * 512));
        asm volatile("cp.async.cg.shared.global [%0], [%1], 16;"
                     :: "r"(db + i * 32 * S2_ROWPAD * 4), "l"(gb + (size_t)i * 32 * 512));
    }
    asm volatile("cp.async.commit_group;" ::: "memory");
}

__global__ void __launch_bounds__(256, 1)
stage2_mma(const float* __restrict__ qtf, const float* __restrict__ Tk,
           const float* __restrict__ score_w, const float* __restrict__ score_b,
           float* __restrict__ other)
{
    extern __shared__ float smf[];
    float* As = smf;
    float* Bs = smf + 2 * S2_TILE;

    const int tid = threadIdx.x;
    const int lane = tid & 31;
    const int wid = tid >> 5;
    const int wm = wid >> 2;
    const int wn = wid & 3;
    const int q0 = blockIdx.y * 128;
    const int c0 = blockIdx.x * 128;

    const int lq = lane >> 2;
    const int ld = lane & 3;

    float sacc[4][4][4];
#pragma unroll
    for (int mi = 0; mi < 4; mi++)
#pragma unroll
        for (int ni = 0; ni < 4; ni++)
#pragma unroll
            for (int r = 0; r < 4; r++) sacc[mi][ni][r] = 0.0f;

    for (int k = 0; k < 8; k++) {
        float macc[4][4][4];
#pragma unroll
        for (int mi = 0; mi < 4; mi++)
#pragma unroll
            for (int ni = 0; ni < 4; ni++)
#pragma unroll
                for (int r = 0; r < 4; r++) macc[mi][ni][r] = 0.0f;

        s2_load(As, Bs, qtf, Tk, q0, c0, tid, k, 0, 0);

        for (int t = 0; t < 16; t++) {
            const int buf = t & 1;
            if (t < 15) {
                s2_load(As, Bs, qtf, Tk, q0, c0, tid, k, t + 1, buf ^ 1);
                asm volatile("cp.async.wait_group 1;" ::: "memory");
            } else {
                asm volatile("cp.async.wait_group 0;" ::: "memory");
            }
            __syncthreads();

            const float* pa = As + buf * S2_TILE;
            const float* pb = Bs + buf * S2_TILE;
#pragma unroll
            for (int d8 = 0; d8 < 4; d8++) {
                float a[4][4], b[4][2];
#pragma unroll
                for (int mi = 0; mi < 4; mi++) {
                    const float* p = pa + (wm * 64 + mi * 16 + lq) * S2_ROWPAD + d8 * 8 + ld;
                    a[mi][0] = p[0];
                    a[mi][1] = p[8 * S2_ROWPAD];
                    a[mi][2] = p[4];
                    a[mi][3] = p[8 * S2_ROWPAD + 4];
                }
#pragma unroll
                for (int ni = 0; ni < 4; ni++) {
                    const float* p = pb + (wn * 32 + ni * 8 + lq) * S2_ROWPAD + d8 * 8 + ld;
                    b[ni][0] = p[0];
                    b[ni][1] = p[4];
                }
#pragma unroll
                for (int mi = 0; mi < 4; mi++)
#pragma unroll
                    for (int ni = 0; ni < 4; ni++)
                        mma_tf32(macc[mi][ni], a[mi], b[ni]);
            }
            __syncthreads();
        }

        const float w = __ldg(score_w + k);
#pragma unroll
        for (int mi = 0; mi < 4; mi++)
#pragma unroll
            for (int ni = 0; ni < 4; ni++)
#pragma unroll
                for (int r = 0; r < 4; r++)
                    sacc[mi][ni][r] = fmaf(fmaxf(macc[mi][ni][r], 0.0f), w, sacc[mi][ni][r]);
    }

    const float sb = __ldg(score_b);
#pragma unroll
    for (int mi = 0; mi < 4; mi++) {
        const int q = q0 + wm * 64 + mi * 16 + lq;
#pragma unroll
        for (int ni = 0; ni < 4; ni++) {
            const int c = c0 + wn * 32 + ni * 8 + 2 * ld;
            float2 v0 = make_float2(sb + sacc[mi][ni][0], sb + sacc[mi][ni][1]);
            float2 v1 = make_float2(sb + sacc[mi][ni][2], sb + sacc[mi][ni][3]);
            *(float2*)(other + (size_t)q * 4096 + c) = v0;
            *(float2*)(other + (size_t)(q + 8) * 4096 + c) = v1;
        }
    }
}

// ---------------------------------------------------------------------------
__global__ void softmax_rows(float* __restrict__ o)
{
    const int row = blockIdx.x;
    float* p = o + (size_t)row * 4096;
    const int tid = threadIdx.x;

    float v[16];
    float mx = -1e30f;
#pragma unroll
    for (int i = 0; i < 16; i++) {
        v[i] = p[tid + (i << 8)];
        mx = fmaxf(mx, v[i]);
    }
    __shared__ float sm[8];
#pragma unroll
    for (int o2 = 16; o2 > 0; o2 >>= 1)
        mx = fmaxf(mx, __shfl_xor_sync(0xffffffffu, mx, o2));
    if ((tid & 31) == 0) sm[tid >> 5] = mx;
    __syncthreads();
    mx = sm[0];
#pragma unroll
    for (int i = 1; i < 8; i++) mx = fmaxf(mx, sm[i]);
    __syncthreads();

    float s = 0.0f;
#pragma unroll
    for (int i = 0; i < 16; i++) { v[i] = expf(v[i] - mx); s += v[i]; }
#pragma unroll
    for (int o2 = 16; o2 > 0; o2 >>= 1)
        s += __shfl_xor_sync(0xffffffffu, s, o2);
    if ((tid & 31) == 0) sm[tid >> 5] = s;
    __syncthreads();
    s = 0.0f;
#pragma unroll
    for (int i = 0; i < 8; i++) s += sm[i];
    float inv = 1.0f / s;
#pragma unroll
    for (int i = 0; i < 16; i++) p[tid + (i << 8)] = v[i] * inv;
}

// ---------------------------------------------------------------------------
// Prep kernels
// ---------------------------------------------------------------------------
__global__ void transpose_hw(const float* __restrict__ hw)
{
    int idx = blockIdx.x * blockDim.x + threadIdx.x;
    int l = idx >> 9;
    int d = idx & 511;
    g_hwT[d * 64 + l] = hw[idx];
}

__global__ void round_query(const float* __restrict__ q)
{
    int idx = blockIdx.x * blockDim.x + threadIdx.x;
    g_qtf[idx] = tf32r(q[idx]);
}

// in [R][C] -> ohi/olo [C][R] with hi/lo tf32 split. block (32,8), grid (C/32, R/32)
__global__ void transpose_split(const float* __restrict__ in,
                                float* __restrict__ ohi, float* __restrict__ olo,
                                int R, int C)
{
    __shared__ float t[32][33];
    const int c0 = blockIdx.x * 32;
    const int r0 = blockIdx.y * 32;
    const int tx = threadIdx.x, ty = threadIdx.y;
#pragma unroll
    for (int i = ty; i < 32; i += 8)
        t[i][tx] = in[(size_t)(r0 + i) * C + c0 + tx];
    __syncthreads();
#pragma unroll
    for (int i = ty; i < 32; i += 8) {
        float v = t[tx][i];
        float hi = tf32r(v);
        size_t o = (size_t)(c0 + i) * R + r0 + tx;
        ohi[o] = hi;
        olo[o] = tf32r(v - hi);
    }
}

// qf = query + sum_z qfp[z]
__global__ void reduce_qf(const float* __restrict__ query)
{
    size_t idx = (size_t)blockIdx.x * blockDim.x + threadIdx.x;  // 0..2097151
    const size_t S = (size_t)4096 * 512;
    g_qf[idx] = query[idx] + g_qfp[idx] + g_qfp[idx + S] +
                g_qfp[idx + 2 * S] + g_qfp[idx + 3 * S];
}

// ---------------------------------------------------------------------------
extern "C" void kernel_launch(void* const* d_in, const int* in_sizes, int n_in,
                              void* d_out, int out_size)
{
    const float* class_v = (const float*)d_in[0];
    const float* query_v = (const float*)d_in[1];
    const float* Mmat    = (const float*)d_in[2];
    const float* score_w = (const float*)d_in[3];
    const float* score_b = (const float*)d_in[4];
    const float* hash_w  = (const float*)d_in[5];
    const float* hash_b  = (const float*)d_in[6];
    float* out = (float*)d_out;

    float *T, *other, *qf, *hwT, *qtf, *mth, *mtl, *cth, *ctl, *qfp;
    cudaGetSymbolAddress((void**)&T, g_T);
    cudaGetSymbolAddress((void**)&other, g_other);
    cudaGetSymbolAddress((void**)&qf, g_qf);
    cudaGetSymbolAddress((void**)&hwT, g_hwT);
    cudaGetSymbolAddress((void**)&qtf, g_qtf);
    cudaGetSymbolAddress((void**)&mth, g_MT_hi);
    cudaGetSymbolAddress((void**)&mtl, g_MT_lo);
    cudaGetSymbolAddress((void**)&cth, g_clT_hi);
    cudaGetSymbolAddress((void**)&ctl, g_clT_lo);
    cudaGetSymbolAddress((void**)&qfp, g_qfp);

    cudaFuncSetAttribute(stage2_mma, cudaFuncAttributeMaxDynamicSharedMemorySize, S2_SMEM);
    cudaFuncSetAttribute(gemm3x<0>, cudaFuncAttributeMaxDynamicSharedMemorySize, G3_SMEM);
    cudaFuncSetAttribute(gemm3x<1>, cudaFuncAttributeMaxDynamicSharedMemorySize, G3_SMEM);

    // prep
    transpose_hw<<<128, 256>>>(hash_w);
    round_query<<<8192, 256>>>(query_v);
    transpose_split<<<dim3(128, 16), dim3(32, 8)>>>(Mmat, mth, mtl, 512, 4096);
    transpose_split<<<dim3(16, 128), dim3(32, 8)>>>(class_v, cth, ctl, 4096, 512);

    // Stage 1: Tk = class @ M (3xTF32, scatter epilogue)
    gemm3x<0><<<dim3(32, 32, 1), 256, G3_SMEM>>>(class_v, mth, mtl, T, 512, 512, 512);

    // Stage 2: fused bilinear + relu + score
    stage2_mma<<<dim3(32, 32), 256, S2_SMEM>>>(qtf, T, score_w, score_b, other);

    // Stage 3: softmax
    softmax_rows<<<4096, 256>>>(other);

    // Stage 4: qf partials = scores @ class (3xTF32, split-K=4), then reduce + residual
    gemm3x<1><<<dim3(4, 32, 4), 256, G3_SMEM>>>(other, cth, ctl, qfp, 4096, 4096, 1024);
    reduce_qf<<<8192, 256>>>(query_v);

    // Stage 5: out = tanh(qf @ hwT + hash_b)
    gemm_f32<64, 64, 16, 4, 4, 2><<<dim3(1, 64), 256>>>(
        qf, hwT, hash_b, out, 4096, 64, 512);
}

// round 7
// speedup vs baseline: 1.0037x; 1.0037x over previous
#include <cuda_runtime.h>
#include <math.h>
#include <stdint.h>

// ---------------------------------------------------------------------------
// Dims: D=512, K=8, L=64, Q=4096, C=4096
//   Tk[k][c][d] = sum_i class[c,i]*M[i,d,k]       (3xTF32 mma GEMM, scatter)
//   other[q,c]  = b + sum_k w_k*relu(sum_d qtf[q,d]*Tk[k][c][d])  (tf32 mma)
//   scores      = softmax_rows(other)
//   qf          = scores @ class + query           (3xTF32 mma, split-K=4)
//   out         = tanh(qf @ hash_w^T + hash_b)     (SIMT GEMM)
// Target sm_103 (no 'a'): mma.sync/cp.async only, no tcgen05.
// ---------------------------------------------------------------------------

__device__ float g_T[(size_t)8 * 4096 * 512];    // 64 MB: Tk[k][c][d]
__device__ float g_other[(size_t)4096 * 4096];   // 64 MB
__device__ float g_qf[(size_t)4096 * 512];       // 8 MB
__device__ float g_qtf[(size_t)4096 * 512];      // 8 MB tf32-rounded query
__device__ float g_hwT[512 * 64];
__device__ float g_MT_hi[(size_t)4096 * 512];    // M^T  [jk][i] hi
__device__ float g_MT_lo[(size_t)4096 * 512];    //               lo
__device__ float g_clT_hi[(size_t)512 * 4096];   // class^T [d][c] hi
__device__ float g_clT_lo[(size_t)512 * 4096];   //               lo
__device__ float g_qfp[(size_t)4 * 4096 * 512];  // 32 MB split-K partials

// ------------------------------ helpers -----------------------------------
__device__ __forceinline__ uint32_t smem_u32(const void* p) {
    uint32_t a;
    asm("{ .reg .u64 t; cvta.to.shared.u64 t, %1; cvt.u32.u64 %0, t; }" : "=r"(a) : "l"(p));
    return a;
}
__device__ __forceinline__ float tf32r(float x) {
    unsigned u;
    asm("cvt.rna.tf32.f32 %0, %1;" : "=r"(u) : "f"(x));
    return __uint_as_float(u);
}
__device__ __forceinline__ void mma_tf32(float* c, const float* a, const float* b) {
    asm volatile(
        "mma.sync.aligned.m16n8k8.row.col.f32.tf32.tf32.f32 "
        "{%0,%1,%2,%3}, {%4,%5,%6,%7}, {%8,%9}, {%0,%1,%2,%3};"
        : "+f"(c[0]), "+f"(c[1]), "+f"(c[2]), "+f"(c[3])
        : "r"(__float_as_uint(a[0])), "r"(__float_as_uint(a[1])),
          "r"(__float_as_uint(a[2])), "r"(__float_as_uint(a[3])),
          "r"(__float_as_uint(b[0])), "r"(__float_as_uint(b[1])));
}

// ---------------------------------------------------------------------------
// Generic tiled fp32 SIMT GEMM (kept for stage 5). EPI 2: tanh(acc + X[c]).
// ---------------------------------------------------------------------------
template <int BM, int BN, int BK, int TM, int TN, int EPI>
__global__ void __launch_bounds__((BM / TM) * (BN / TN), 2)
gemm_f32(const float* __restrict__ A, const float* __restrict__ B,
         const float* __restrict__ X, float* __restrict__ out,
         int M, int N, int K)
{
    constexpr int THREADS = (BM / TM) * (BN / TN);
    __shared__ float As[BK][BM + 4];
    __shared__ float Bs[BK][BN + 4];

    const int bm = blockIdx.y * BM;
    const int bn = blockIdx.x * BN;
    const int tid = threadIdx.x;
    const int tcol = tid % (BN / TN);
    const int trow = tid / (BN / TN);

    float acc[TM][TN];
#pragma unroll
    for (int i = 0; i < TM; i++)
#pragma unroll
        for (int j = 0; j < TN; j++) acc[i][j] = 0.0f;

    for (int k0 = 0; k0 < K; k0 += BK) {
#pragma unroll
        for (int it = 0; it < (BM * BK / 4) / THREADS; it++) {
            int i = tid + it * THREADS;
            int r = i / (BK / 4);
            int c4 = (i % (BK / 4)) * 4;
            float4 v = *(const float4*)(A + (size_t)(bm + r) * K + k0 + c4);
            As[c4 + 0][r] = v.x; As[c4 + 1][r] = v.y;
            As[c4 + 2][r] = v.z; As[c4 + 3][r] = v.w;
        }
#pragma unroll
        for (int it = 0; it < (BK * BN / 4) / THREADS; it++) {
            int i = tid + it * THREADS;
            int r = i / (BN / 4);
            int c4 = (i % (BN / 4)) * 4;
            *(float4*)&Bs[r][c4] = *(const float4*)(B + (size_t)(k0 + r) * N + bn + c4);
        }
        __syncthreads();

#pragma unroll
        for (int kk = 0; kk < BK; kk++) {
            float af[TM], bf[TN];
#pragma unroll
            for (int i = 0; i < TM; i += 4) {
                float4 v = *(const float4*)&As[kk][trow * TM + i];
                af[i] = v.x; af[i + 1] = v.y; af[i + 2] = v.z; af[i + 3] = v.w;
            }
#pragma unroll
            for (int j = 0; j < TN; j += 4) {
                float4 v = *(const float4*)&Bs[kk][tcol * TN + j];
                bf[j] = v.x; bf[j + 1] = v.y; bf[j + 2] = v.z; bf[j + 3] = v.w;
            }
#pragma unroll
            for (int i = 0; i < TM; i++)
#pragma unroll
                for (int j = 0; j < TN; j++)
                    acc[i][j] = fmaf(af[i], bf[j], acc[i][j]);
        }
        __syncthreads();
    }

#pragma unroll
    for (int i = 0; i < TM; i++) {
        int r = bm + trow * TM + i;
#pragma unroll
        for (int j = 0; j < TN; j++) {
            int c = bn + tcol * TN + j;
            float v = acc[i][j];
            if (EPI == 2) v = tanhf(v + X[c]);
            out[(size_t)r * N + c] = v;
        }
    }
}

// ---------------------------------------------------------------------------
// 3xTF32 mma GEMM: out = A[M,Kr] @ Bt[N,Kr]^T, near-fp32 accuracy.
// A fp32 (hi/lo split in registers); Bt pre-split into Bhi/Blo.
// CTA 128m x 128n, 8 warps (2x4), warp tile 64x32, chunk=32, double buffer.
// kseg: reduction length per z-slice; kstart = z*kseg.
//   EPI 0: scatter tf32r(v) to Tk layout ((c&7)<<21) + r*512 + (c>>3)
//   EPI 1: store partial to out + z*4096*512 at [r*512+c]
// ---------------------------------------------------------------------------
#define G3_PAD 36
#define G3_TILE (128 * G3_PAD)
#define G3_SMEM (6 * G3_TILE * 4)   // 110592 B

template <int EPI>
__device__ __forceinline__ void g3_load(float* As, float* Bh, float* Bl,
                                        const float* __restrict__ A,
                                        const float* __restrict__ Bhi,
                                        const float* __restrict__ Blo,
                                        int m0, int n0, int lda, int ldb,
                                        int kofs, int tid, int buf)
{
    const int row = tid >> 3;
    const int f4 = (tid & 7) * 4;
    uint32_t da = smem_u32(As + buf * G3_TILE + row * G3_PAD + f4);
    uint32_t dh = smem_u32(Bh + buf * G3_TILE + row * G3_PAD + f4);
    uint32_t dl = smem_u32(Bl + buf * G3_TILE + row * G3_PAD + f4);
    const float* ga = A + (size_t)(m0 + row) * lda + kofs + f4;
    const float* gh = Bhi + (size_t)(n0 + row) * ldb + kofs + f4;
    const float* gl = Blo + (size_t)(n0 + row) * ldb + kofs + f4;
#pragma unroll
    for (int i = 0; i < 4; i++) {
        asm volatile("cp.async.cg.shared.global [%0], [%1], 16;"
                     :: "r"(da + i * 32 * G3_PAD * 4), "l"(ga + (size_t)i * 32 * lda));
        asm volatile("cp.async.cg.shared.global [%0], [%1], 16;"
                     :: "r"(dh + i * 32 * G3_PAD * 4), "l"(gh + (size_t)i * 32 * ldb));
        asm volatile("cp.async.cg.shared.global [%0], [%1], 16;"
                     :: "r"(dl + i * 32 * G3_PAD * 4), "l"(gl + (size_t)i * 32 * ldb));
    }
    asm volatile("cp.async.commit_group;" ::: "memory");
}

template <int EPI>
__global__ void __launch_bounds__(256, 1)
gemm3x(const float* __restrict__ A,
       const float* __restrict__ Bhi, const float* __restrict__ Blo,
       float* __restrict__ out, int lda, int ldb, int kseg)
{
    extern __shared__ float smf[];
    float* As = smf;
    float* Bh = smf + 2 * G3_TILE;
    float* Bl = smf + 4 * G3_TILE;

    const int tid = threadIdx.x;
    const int lane = tid & 31;
    const int wid = tid >> 5;
    const int wm = wid >> 2;
    const int wn = wid & 3;
    const int m0 = blockIdx.y * 128;
    const int n0 = blockIdx.x * 128;
    const int kstart = blockIdx.z * kseg;
    const int nchunks = kseg / 32;

    const int lq = lane >> 2;
    const int ld = lane & 3;

    float macc[4][4][4];
#pragma unroll
    for (int mi = 0; mi < 4; mi++)
#pragma unroll
        for (int ni = 0; ni < 4; ni++)
#pragma unroll
            for (int r = 0; r < 4; r++) macc[mi][ni][r] = 0.0f;

    g3_load<EPI>(As, Bh, Bl, A, Bhi, Blo, m0, n0, lda, ldb, kstart, tid, 0);

    for (int t = 0; t < nchunks; t++) {
        const int buf = t & 1;
        if (t < nchunks - 1) {
            g3_load<EPI>(As, Bh, Bl, A, Bhi, Blo, m0, n0, lda, ldb,
                         kstart + (t + 1) * 32, tid, buf ^ 1);
            asm volatile("cp.async.wait_group 1;" ::: "memory");
        } else {
            asm volatile("cp.async.wait_group 0;" ::: "memory");
        }
        __syncthreads();

        const float* pa = As + buf * G3_TILE;
        const float* ph = Bh + buf * G3_TILE;
        const float* pl = Bl + buf * G3_TILE;
#pragma unroll
        for (int d8 = 0; d8 < 4; d8++) {
            float ahi[4][4], alo[4][4];
#pragma unroll
            for (int mi = 0; mi < 4; mi++) {
                const float* p = pa + (wm * 64 + mi * 16 + lq) * G3_PAD + d8 * 8 + ld;
                float a0 = p[0], a1 = p[8 * G3_PAD], a2 = p[4], a3 = p[8 * G3_PAD + 4];
                ahi[mi][0] = tf32r(a0); alo[mi][0] = tf32r(a0 - ahi[mi][0]);
                ahi[mi][1] = tf32r(a1); alo[mi][1] = tf32r(a1 - ahi[mi][1]);
                ahi[mi][2] = tf32r(a2); alo[mi][2] = tf32r(a2 - ahi[mi][2]);
                ahi[mi][3] = tf32r(a3); alo[mi][3] = tf32r(a3 - ahi[mi][3]);
            }
            float bh[4][2], bl[4][2];
#pragma unroll
            for (int ni = 0; ni < 4; ni++) {
                const float* p = ph + (wn * 32 + ni * 8 + lq) * G3_PAD + d8 * 8 + ld;
                bh[ni][0] = p[0]; bh[ni][1] = p[4];
                const float* p2 = pl + (wn * 32 + ni * 8 + lq) * G3_PAD + d8 * 8 + ld;
                bl[ni][0] = p2[0]; bl[ni][1] = p2[4];
            }
#pragma unroll
            for (int mi = 0; mi < 4; mi++)
#pragma unroll
                for (int ni = 0; ni < 4; ni++) {
                    mma_tf32(macc[mi][ni], ahi[mi], bh[ni]);
                    mma_tf32(macc[mi][ni], alo[mi], bh[ni]);
                    mma_tf32(macc[mi][ni], ahi[mi], bl[ni]);
                }
        }
        __syncthreads();
    }

    // epilogue
    if (EPI == 0) {
#pragma unroll
        for (int mi = 0; mi < 4; mi++) {
            const int r = m0 + wm * 64 + mi * 16 + lq;
#pragma unroll
            for (int ni = 0; ni < 4; ni++) {
                const int c = n0 + wn * 32 + ni * 8 + 2 * ld;
#pragma unroll
                for (int rr = 0; rr < 4; rr++) {
                    int row = r + (rr >> 1) * 8;
                    int col = c + (rr & 1);
                    size_t idx = ((size_t)(col & 7) << 21) + (size_t)row * 512 + (size_t)(col >> 3);
                    out[idx] = tf32r(macc[mi][ni][rr]);
                }
            }
        }
    } else {
        float* ob = out + (size_t)blockIdx.z * 4096 * 512;
#pragma unroll
        for (int mi = 0; mi < 4; mi++) {
            const int r = m0 + wm * 64 + mi * 16 + lq;
#pragma unroll
            for (int ni = 0; ni < 4; ni++) {
                const int c = n0 + wn * 32 + ni * 8 + 2 * ld;
                *(float2*)(ob + (size_t)r * 512 + c) =
                    make_float2(macc[mi][ni][0], macc[mi][ni][1]);
                *(float2*)(ob + (size_t)(r + 8) * 512 + c) =
                    make_float2(macc[mi][ni][2], macc[mi][ni][3]);
            }
        }
    }
}

// ---------------------------------------------------------------------------
// Stage 2: mma.sync tf32 fused bilinear + relu + score. (unchanged from R4)
// ---------------------------------------------------------------------------
#define S2_ROWPAD 36
#define S2_TILE (128 * S2_ROWPAD)
#define S2_SMEM (4 * S2_TILE * 4)

__device__ __forceinline__ void s2_load(float* As, float* Bs,
                                        const float* __restrict__ qtf,
                                        const float* __restrict__ Tk,
                                        int q0, int c0, int tid, int k, int t, int buf)
{
    const int row = tid >> 3;
    const int f4 = (tid & 7) * 4;
    const float* ga = qtf + (size_t)(q0 + row) * 512 + t * 32 + f4;
    const float* gb = Tk + ((size_t)k << 21) + (size_t)(c0 + row) * 512 + t * 32 + f4;
    uint32_t da = smem_u32(As + buf * S2_TILE + row * S2_ROWPAD + f4);
    uint32_t db = smem_u32(Bs + buf * S2_TILE + row * S2_ROWPAD + f4);
#pragma unroll
    for (int i = 0; i < 4; i++) {
        asm volatile("cp.async.cg.shared.global [%0], [%1], 16;"
                     :: "r"(da + i * 32 * S2_ROWPAD * 4), "l"(ga + (size_t)i * 32 * 512));
        asm volatile("cp.async.cg.shared.global [%0], [%1], 16;"
                     :: "r"(db + i * 32 * S2_ROWPAD * 4), "l"(gb + (size_t)i * 32 * 512));
    }
    asm volatile("cp.async.commit_group;" ::: "memory");
}

__global__ void __launch_bounds__(256, 1)
stage2_mma(const float* __restrict__ qtf, const float* __restrict__ Tk,
           const float* __restrict__ score_w, const float* __restrict__ score_b,
           float* __restrict__ other)
{
    extern __shared__ float smf[];
    float* As = smf;
    float* Bs = smf + 2 * S2_TILE;

    const int tid = threadIdx.x;
    const int lane = tid & 31;
    const int wid = tid >> 5;
    const int wm = wid >> 2;
    const int wn = wid & 3;
    const int q0 = blockIdx.y * 128;
    const int c0 = blockIdx.x * 128;

    const int lq = lane >> 2;
    const int ld = lane & 3;

    float sacc[4][4][4];
#pragma unroll
    for (int mi = 0; mi < 4; mi++)
#pragma unroll
        for (int ni = 0; ni < 4; ni++)
#pragma unroll
            for (int r = 0; r < 4; r++) sacc[mi][ni][r] = 0.0f;

    for (int k = 0; k < 8; k++) {
        float macc[4][4][4];
#pragma unroll
        for (int mi = 0; mi < 4; mi++)
#pragma unroll
            for (int ni = 0; ni < 4; ni++)
#pragma unroll
                for (int r = 0; r < 4; r++) macc[mi][ni][r] = 0.0f;

        s2_load(As, Bs, qtf, Tk, q0, c0, tid, k, 0, 0);

        for (int t = 0; t < 16; t++) {
            const int buf = t & 1;
            if (t < 15) {
                s2_load(As, Bs, qtf, Tk, q0, c0, tid, k, t + 1, buf ^ 1);
                asm volatile("cp.async.wait_group 1;" ::: "memory");
            } else {
                asm volatile("cp.async.wait_group 0;" ::: "memory");
            }
            __syncthreads();

            const float* pa = As + buf * S2_TILE;
            const float* pb = Bs + buf * S2_TILE;
#pragma unroll
            for (int d8 = 0; d8 < 4; d8++) {
                float a[4][4], b[4][2];
#pragma unroll
                for (int mi = 0; mi < 4; mi++) {
                    const float* p = pa + (wm * 64 + mi * 16 + lq) * S2_ROWPAD + d8 * 8 + ld;
                    a[mi][0] = p[0];
                    a[mi][1] = p[8 * S2_ROWPAD];
                    a[mi][2] = p[4];
                    a[mi][3] = p[8 * S2_ROWPAD + 4];
                }
#pragma unroll
                for (int ni = 0; ni < 4; ni++) {
                    const float* p = pb + (wn * 32 + ni * 8 + lq) * S2_ROWPAD + d8 * 8 + ld;
                    b[ni][0] = p[0];
                    b[ni][1] = p[4];
                }
#pragma unroll
                for (int mi = 0; mi < 4; mi++)
#pragma unroll
                    for (int ni = 0; ni < 4; ni++)
                        mma_tf32(macc[mi][ni], a[mi], b[ni]);
            }
            __syncthreads();
        }

        const float w = __ldg(score_w + k);
#pragma unroll
        for (int mi = 0; mi < 4; mi++)
#pragma unroll
            for (int ni = 0; ni < 4; ni++)
#pragma unroll
                for (int r = 0; r < 4; r++)
                    sacc[mi][ni][r] = fmaf(fmaxf(macc[mi][ni][r], 0.0f), w, sacc[mi][ni][r]);
    }

    const float sb = __ldg(score_b);
#pragma unroll
    for (int mi = 0; mi < 4; mi++) {
        const int q = q0 + wm * 64 + mi * 16 + lq;
#pragma unroll
        for (int ni = 0; ni < 4; ni++) {
            const int c = c0 + wn * 32 + ni * 8 + 2 * ld;
            float2 v0 = make_float2(sb + sacc[mi][ni][0], sb + sacc[mi][ni][1]);
            float2 v1 = make_float2(sb + sacc[mi][ni][2], sb + sacc[mi][ni][3]);
            *(float2*)(other + (size_t)q * 4096 + c) = v0;
            *(float2*)(other + (size_t)(q + 8) * 4096 + c) = v1;
        }
    }
}

// ---------------------------------------------------------------------------
__global__ void softmax_rows(float* __restrict__ o)
{
    const int row = blockIdx.x;
    float* p = o + (size_t)row * 4096;
    const int tid = threadIdx.x;

    float v[16];
    float mx = -1e30f;
#pragma unroll
    for (int i = 0; i < 16; i++) {
        v[i] = p[tid + (i << 8)];
        mx = fmaxf(mx, v[i]);
    }
    __shared__ float sm[8];
#pragma unroll
    for (int o2 = 16; o2 > 0; o2 >>= 1)
        mx = fmaxf(mx, __shfl_xor_sync(0xffffffffu, mx, o2));
    if ((tid & 31) == 0) sm[tid >> 5] = mx;
    __syncthreads();
    mx = sm[0];
#pragma unroll
    for (int i = 1; i < 8; i++) mx = fmaxf(mx, sm[i]);
    __syncthreads();

    float s = 0.0f;
#pragma unroll
    for (int i = 0; i < 16; i++) { v[i] = expf(v[i] - mx); s += v[i]; }
#pragma unroll
    for (int o2 = 16; o2 > 0; o2 >>= 1)
        s += __shfl_xor_sync(0xffffffffu, s, o2);
    if ((tid & 31) == 0) sm[tid >> 5] = s;
    __syncthreads();
    s = 0.0f;
#pragma unroll
    for (int i = 0; i < 8; i++) s += sm[i];
    float inv = 1.0f / s;
#pragma unroll
    for (int i = 0; i < 16; i++) p[tid + (i << 8)] = v[i] * inv;
}

// ---------------------------------------------------------------------------
// Prep kernels
// ---------------------------------------------------------------------------
__global__ void transpose_hw(const float* __restrict__ hw)
{
    int idx = blockIdx.x * blockDim.x + threadIdx.x;
    int l = idx >> 9;
    int d = idx & 511;
    g_hwT[d * 64 + l] = hw[idx];
}

__global__ void round_query(const float* __restrict__ q)
{
    int idx = blockIdx.x * blockDim.x + threadIdx.x;
    g_qtf[idx] = tf32r(q[idx]);
}

// in [R][C] -> ohi/olo [C][R] with hi/lo tf32 split. block (32,8), grid (C/32, R/32)
__global__ void transpose_split(const float* __restrict__ in,
                                float* __restrict__ ohi, float* __restrict__ olo,
                                int R, int C)
{
    __shared__ float t[32][33];
    const int c0 = blockIdx.x * 32;
    const int r0 = blockIdx.y * 32;
    const int tx = threadIdx.x, ty = threadIdx.y;
#pragma unroll
    for (int i = ty; i < 32; i += 8)
        t[i][tx] = in[(size_t)(r0 + i) * C + c0 + tx];
    __syncthreads();
#pragma unroll
    for (int i = ty; i < 32; i += 8) {
        float v = t[tx][i];
        float hi = tf32r(v);
        size_t o = (size_t)(c0 + i) * R + r0 + tx;
        ohi[o] = hi;
        olo[o] = tf32r(v - hi);
    }
}

// qf = query + sum_z qfp[z]
__global__ void reduce_qf(const float* __restrict__ query)
{
    size_t idx = (size_t)blockIdx.x * blockDim.x + threadIdx.x;  // 0..2097151
    const size_t S = (size_t)4096 * 512;
    g_qf[idx] = query[idx] + g_qfp[idx] + g_qfp[idx + S] +
                g_qfp[idx + 2 * S] + g_qfp[idx + 3 * S];
}

// ---------------------------------------------------------------------------
extern "C" void kernel_launch(void* const* d_in, const int* in_sizes, int n_in,
                              void* d_out, int out_size)
{
    const float* class_v = (const float*)d_in[0];
    const float* query_v = (const float*)d_in[1];
    const float* Mmat    = (const float*)d_in[2];
    const float* score_w = (const float*)d_in[3];
    const float* score_b = (const float*)d_in[4];
    const float* hash_w  = (const float*)d_in[5];
    const float* hash_b  = (const float*)d_in[6];
    float* out = (float*)d_out;

    float *T, *other, *qf, *hwT, *qtf, *mth, *mtl, *cth, *ctl, *qfp;
    cudaGetSymbolAddress((void**)&T, g_T);
    cudaGetSymbolAddress((void**)&other, g_other);
    cudaGetSymbolAddress((void**)&qf, g_qf);
    cudaGetSymbolAddress((void**)&hwT, g_hwT);
    cudaGetSymbolAddress((void**)&qtf, g_qtf);
    cudaGetSymbolAddress((void**)&mth, g_MT_hi);
    cudaGetSymbolAddress((void**)&mtl, g_MT_lo);
    cudaGetSymbolAddress((void**)&cth, g_clT_hi);
    cudaGetSymbolAddress((void**)&ctl, g_clT_lo);
    cudaGetSymbolAddress((void**)&qfp, g_qfp);

    cudaFuncSetAttribute(stage2_mma, cudaFuncAttributeMaxDynamicSharedMemorySize, S2_SMEM);
    cudaFuncSetAttribute(gemm3x<0>, cudaFuncAttributeMaxDynamicSharedMemorySize, G3_SMEM);
    cudaFuncSetAttribute(gemm3x<1>, cudaFuncAttributeMaxDynamicSharedMemorySize, G3_SMEM);

    // prep
    transpose_hw<<<128, 256>>>(hash_w);
    round_query<<<8192, 256>>>(query_v);
    transpose_split<<<dim3(128, 16), dim3(32, 8)>>>(Mmat, mth, mtl, 512, 4096);
    transpose_split<<<dim3(16, 128), dim3(32, 8)>>>(class_v, cth, ctl, 4096, 512);

    // Stage 1: Tk = class @ M (3xTF32, scatter epilogue)
    gemm3x<0><<<dim3(32, 32, 1), 256, G3_SMEM>>>(class_v, mth, mtl, T, 512, 512, 512);

    // Stage 2: fused bilinear + relu + score
    stage2_mma<<<dim3(32, 32), 256, S2_SMEM>>>(qtf, T, score_w, score_b, other);

    // Stage 3: softmax
    softmax_rows<<<4096, 256>>>(other);

    // Stage 4: qf partials = scores @ class (3xTF32, split-K=4), then reduce + residual
    gemm3x<1><<<dim3(4, 32, 4), 256, G3_SMEM>>>(other, cth, ctl, qfp, 4096, 4096, 1024);
    reduce_qf<<<8192, 256>>>(query_v);

    // Stage 5: out = tanh(qf @ hwT + hash_b)
    gemm_f32<64, 64, 16, 4, 4, 2><<<dim3(1, 64), 256>>>(
        qf, hwT, hash_b, out, 4096, 64, 512);
}

// round 8
// speedup vs baseline: 1.1850x; 1.1806x over previous
#include <cuda_runtime.h>
#include <math.h>
#include <stdint.h>

// ---------------------------------------------------------------------------
// Dims: D=512, K=8, L=64, Q=4096, C=4096
//   Tk (B-frag packed)  = class @ M        (3xTF32 mma, packed-scatter epi)
//   other[q,c] = b + sum_k w_k*relu(sum_d q.T)   (tf32 mma, frag-packed operands)
//   scores     = softmax_rows(other)
//   qf         = scores @ class + query    (3xTF32 mma, split-K=4)
//   out        = tanh(qf @ hash_w^T + b)   (SIMT GEMM)
// Target sm_103 (no 'a'): mma.sync/cp.async only.
//
// Fragment packing conventions (m16n8k8 tf32 row.col):
//  A-frag (16q x 8d): 128 floats; lane L (lq=L>>2, ld=L&3) holds j=0..3 at L*4:
//     j -> (q̂ = lq + 8*(j&1), d̂ = ld + 4*(j>>1))
//  B-frag (8n x 8k): 64 floats; lane L holds slot s=0..1 at L*2:
//     s -> (n̂ = lq, k̂ = ld + 4*s)
// A chunk (128q x 32d) = 32 frags (r16*4+d8) * 128 floats = 16KB contiguous.
// B chunk (128n x 32k) = 64 frags (nfrag*4+k8) * 64 floats = 16KB contiguous.
// ---------------------------------------------------------------------------

__device__ float g_T[(size_t)8 * 4096 * 512];    // Tk B-frag packed per k slab
__device__ float g_other[(size_t)4096 * 4096];
__device__ float g_qf[(size_t)4096 * 512];
__device__ float g_qtf[(size_t)4096 * 512];      // query, A-frag packed, tf32
__device__ float g_hwT[512 * 64];
__device__ float g_MT_hi[(size_t)4096 * 512];    // M^T packed-B hi
__device__ float g_MT_lo[(size_t)4096 * 512];
__device__ float g_clT_hi[(size_t)512 * 4096];   // class^T packed-B hi
__device__ float g_clT_lo[(size_t)512 * 4096];
__device__ float g_qfp[(size_t)4 * 4096 * 512];  // split-K partials

// ------------------------------ helpers -----------------------------------
__device__ __forceinline__ uint32_t smem_u32(const void* p) {
    uint32_t a;
    asm("{ .reg .u64 t; cvta.to.shared.u64 t, %1; cvt.u32.u64 %0, t; }" : "=r"(a) : "l"(p));
    return a;
}
__device__ __forceinline__ float tf32r(float x) {
    unsigned u;
    asm("cvt.rna.tf32.f32 %0, %1;" : "=r"(u) : "f"(x));
    return __uint_as_float(u);
}
__device__ __forceinline__ void mma_tf32(float* c, const float* a, const float* b) {
    asm volatile(
        "mma.sync.aligned.m16n8k8.row.col.f32.tf32.tf32.f32 "
        "{%0,%1,%2,%3}, {%4,%5,%6,%7}, {%8,%9}, {%0,%1,%2,%3};"
        : "+f"(c[0]), "+f"(c[1]), "+f"(c[2]), "+f"(c[3])
        : "r"(__float_as_uint(a[0])), "r"(__float_as_uint(a[1])),
          "r"(__float_as_uint(a[2])), "r"(__float_as_uint(a[3])),
          "r"(__float_as_uint(b[0])), "r"(__float_as_uint(b[1])));
}
// packed-B offset for element (n, k) with reduction length Ktot
__device__ __forceinline__ size_t bpack_off(int n, int k, int Ktot) {
    return ((size_t)(n >> 7) * (Ktot >> 5) + (k >> 5)) * 4096
         + ((((n >> 3) & 15) << 2) + ((k >> 3) & 3)) * 64
         + (((n & 7) << 2) + (k & 3)) * 2 + ((k >> 2) & 1);
}

// ---------------------------------------------------------------------------
// SIMT GEMM for stage 5 only. EPI 2: tanh(acc + X[c]).
// ---------------------------------------------------------------------------
template <int BM, int BN, int BK, int TM, int TN, int EPI>
__global__ void __launch_bounds__((BM / TM) * (BN / TN), 2)
gemm_f32(const float* __restrict__ A, const float* __restrict__ B,
         const float* __restrict__ X, float* __restrict__ out,
         int M, int N, int K)
{
    constexpr int THREADS = (BM / TM) * (BN / TN);
    __shared__ float As[BK][BM + 4];
    __shared__ float Bs[BK][BN + 4];

    const int bm = blockIdx.y * BM;
    const int bn = blockIdx.x * BN;
    const int tid = threadIdx.x;
    const int tcol = tid % (BN / TN);
    const int trow = tid / (BN / TN);

    float acc[TM][TN];
#pragma unroll
    for (int i = 0; i < TM; i++)
#pragma unroll
        for (int j = 0; j < TN; j++) acc[i][j] = 0.0f;

    for (int k0 = 0; k0 < K; k0 += BK) {
#pragma unroll
        for (int it = 0; it < (BM * BK / 4) / THREADS; it++) {
            int i = tid + it * THREADS;
            int r = i / (BK / 4);
            int c4 = (i % (BK / 4)) * 4;
            float4 v = *(const float4*)(A + (size_t)(bm + r) * K + k0 + c4);
            As[c4 + 0][r] = v.x; As[c4 + 1][r] = v.y;
            As[c4 + 2][r] = v.z; As[c4 + 3][r] = v.w;
        }
#pragma unroll
        for (int it = 0; it < (BK * BN / 4) / THREADS; it++) {
            int i = tid + it * THREADS;
            int r = i / (BN / 4);
            int c4 = (i % (BN / 4)) * 4;
            *(float4*)&Bs[r][c4] = *(const float4*)(B + (size_t)(k0 + r) * N + bn + c4);
        }
        __syncthreads();

#pragma unroll
        for (int kk = 0; kk < BK; kk++) {
            float af[TM], bf[TN];
#pragma unroll
            for (int i = 0; i < TM; i += 4) {
                float4 v = *(const float4*)&As[kk][trow * TM + i];
                af[i] = v.x; af[i + 1] = v.y; af[i + 2] = v.z; af[i + 3] = v.w;
            }
#pragma unroll
            for (int j = 0; j < TN; j += 4) {
                float4 v = *(const float4*)&Bs[kk][tcol * TN + j];
                bf[j] = v.x; bf[j + 1] = v.y; bf[j + 2] = v.z; bf[j + 3] = v.w;
            }
#pragma unroll
            for (int i = 0; i < TM; i++)
#pragma unroll
                for (int j = 0; j < TN; j++)
                    acc[i][j] = fmaf(af[i], bf[j], acc[i][j]);
        }
        __syncthreads();
    }

#pragma unroll
    for (int i = 0; i < TM; i++) {
        int r = bm + trow * TM + i;
#pragma unroll
        for (int j = 0; j < TN; j++) {
            int c = bn + tcol * TN + j;
            float v = acc[i][j];
            if (EPI == 2) v = tanhf(v + X[c]);
            out[(size_t)r * N + c] = v;
        }
    }
}

// ---------------------------------------------------------------------------
// 3xTF32 mma GEMM (stages 1 & 4): out = A[M,Kr] @ Bt[N,Kr]^T.
// A fp32 row-major (split in regs); B pre-split & fragment-packed (hi/lo).
//   EPI 0: scatter tf32r(v) to Tk B-frag-packed layout (Ktot_out = 512)
//   EPI 1: store partial to out + z*4096*512
// ---------------------------------------------------------------------------
#define G3_PAD 36
#define G3_ATILE (128 * G3_PAD)                      // 4608 floats per buf
#define G3_BH0 (2 * G3_ATILE)                        // 9216
#define G3_BL0 (G3_BH0 + 2 * 4096)                   // 17408
#define G3_SMEM ((G3_BL0 + 2 * 4096) * 4)            // 102400 B

__device__ __forceinline__ void g3_load(float* smf,
                                        const float* __restrict__ A,
                                        const float* __restrict__ Bhi,
                                        const float* __restrict__ Blo,
                                        int m0, int n0, int lda, int Ktot,
                                        int kofs, int tid, int buf)
{
    // A: 128 rows x 32 cols, padded rows
    const int row = tid >> 3;
    const int f4 = (tid & 7) * 4;
    uint32_t da = smem_u32(smf + buf * G3_ATILE + row * G3_PAD + f4);
    const float* ga = A + (size_t)(m0 + row) * lda + kofs + f4;
#pragma unroll
    for (int i = 0; i < 4; i++)
        asm volatile("cp.async.cg.shared.global [%0], [%1], 16;"
                     :: "r"(da + i * 32 * G3_PAD * 4), "l"(ga + (size_t)i * 32 * lda));
    // B hi/lo: contiguous 16KB packed chunks
    const size_t bofs = ((size_t)(n0 >> 7) * (Ktot >> 5) + (kofs >> 5)) * 4096;
    uint32_t dh = smem_u32(smf + G3_BH0 + buf * 4096 + tid * 4);
    uint32_t dl = smem_u32(smf + G3_BL0 + buf * 4096 + tid * 4);
    const float* gh = Bhi + bofs + tid * 4;
    const float* gl = Blo + bofs + tid * 4;
#pragma unroll
    for (int i = 0; i < 4; i++) {
        asm volatile("cp.async.cg.shared.global [%0], [%1], 16;"
                     :: "r"(dh + i * 4096), "l"(gh + i * 1024));
        asm volatile("cp.async.cg.shared.global [%0], [%1], 16;"
                     :: "r"(dl + i * 4096), "l"(gl + i * 1024));
    }
    asm volatile("cp.async.commit_group;" ::: "memory");
}

template <int EPI>
__global__ void __launch_bounds__(256, 1)
gemm3x(const float* __restrict__ A,
       const float* __restrict__ Bhi, const float* __restrict__ Blo,
       float* __restrict__ out, int lda, int Ktot, int kseg)
{
    extern __shared__ float smf[];

    const int tid = threadIdx.x;
    const int lane = tid & 31;
    const int wid = tid >> 5;
    const int wm = wid >> 2;
    const int wn = wid & 3;
    const int m0 = blockIdx.y * 128;
    const int n0 = blockIdx.x * 128;
    const int kstart = blockIdx.z * kseg;
    const int nchunks = kseg / 32;

    const int lq = lane >> 2;
    const int ld = lane & 3;

    float macc[4][4][4];
#pragma unroll
    for (int mi = 0; mi < 4; mi++)
#pragma unroll
        for (int ni = 0; ni < 4; ni++)
#pragma unroll
            for (int r = 0; r < 4; r++) macc[mi][ni][r] = 0.0f;

    g3_load(smf, A, Bhi, Blo, m0, n0, lda, Ktot, kstart, tid, 0);

    for (int t = 0; t < nchunks; t++) {
        const int buf = t & 1;
        if (t < nchunks - 1) {
            g3_load(smf, A, Bhi, Blo, m0, n0, lda, Ktot,
                    kstart + (t + 1) * 32, tid, buf ^ 1);
            asm volatile("cp.async.wait_group 1;" ::: "memory");
        } else {
            asm volatile("cp.async.wait_group 0;" ::: "memory");
        }
        __syncthreads();

        const float* pa = smf + buf * G3_ATILE;
        const float* ph = smf + G3_BH0 + buf * 4096;
        const float* pl = smf + G3_BL0 + buf * 4096;
#pragma unroll
        for (int d8 = 0; d8 < 4; d8++) {
            float ahi[4][4], alo[4][4];
#pragma unroll
            for (int mi = 0; mi < 4; mi++) {
                const float* p = pa + (wm * 64 + mi * 16 + lq) * G3_PAD + d8 * 8 + ld;
                float a0 = p[0], a1 = p[8 * G3_PAD], a2 = p[4], a3 = p[8 * G3_PAD + 4];
                ahi[mi][0] = tf32r(a0); alo[mi][0] = tf32r(a0 - ahi[mi][0]);
                ahi[mi][1] = tf32r(a1); alo[mi][1] = tf32r(a1 - ahi[mi][1]);
                ahi[mi][2] = tf32r(a2); alo[mi][2] = tf32r(a2 - ahi[mi][2]);
                ahi[mi][3] = tf32r(a3); alo[mi][3] = tf32r(a3 - ahi[mi][3]);
            }
            float2 bh[4], bl[4];
#pragma unroll
            for (int ni = 0; ni < 4; ni++) {
                int fo = ((wn * 4 + ni) * 4 + d8) * 64 + lane * 2;
                bh[ni] = *(const float2*)(ph + fo);
                bl[ni] = *(const float2*)(pl + fo);
            }
#pragma unroll
            for (int mi = 0; mi < 4; mi++)
#pragma unroll
                for (int ni = 0; ni < 4; ni++) {
                    mma_tf32(macc[mi][ni], ahi[mi], (const float*)&bh[ni]);
                    mma_tf32(macc[mi][ni], alo[mi], (const float*)&bh[ni]);
                    mma_tf32(macc[mi][ni], ahi[mi], (const float*)&bl[ni]);
                }
        }
        __syncthreads();
    }

    if (EPI == 0) {
        // scatter to Tk: out column = j*8+k' -> slab k', (c=row, d=col>>3),
        // packed B layout with Ktot_out = 512
#pragma unroll
        for (int mi = 0; mi < 4; mi++) {
            const int r = m0 + wm * 64 + mi * 16 + lq;
#pragma unroll
            for (int ni = 0; ni < 4; ni++) {
                const int c = n0 + wn * 32 + ni * 8 + 2 * ld;
#pragma unroll
                for (int rr = 0; rr < 4; rr++) {
                    int row = r + (rr >> 1) * 8;
                    int col = c + (rr & 1);
                    int kp = col & 7, dd = col >> 3;
                    size_t idx = ((size_t)kp << 21) + bpack_off(row, dd, 512);
                    out[idx] = tf32r(macc[mi][ni][rr]);
                }
            }
        }
    } else {
        float* ob = out + (size_t)blockIdx.z * 4096 * 512;
#pragma unroll
        for (int mi = 0; mi < 4; mi++) {
            const int r = m0 + wm * 64 + mi * 16 + lq;
#pragma unroll
            for (int ni = 0; ni < 4; ni++) {
                const int c = n0 + wn * 32 + ni * 8 + 2 * ld;
                *(float2*)(ob + (size_t)r * 512 + c) =
                    make_float2(macc[mi][ni][0], macc[mi][ni][1]);
                *(float2*)(ob + (size_t)(r + 8) * 512 + c) =
                    make_float2(macc[mi][ni][2], macc[mi][ni][3]);
            }
        }
    }
}

// ---------------------------------------------------------------------------
// Stage 2: fused bilinear + relu + score, fragment-packed operands,
// 4-stage cp.async pipeline, one __syncthreads per chunk.
// ---------------------------------------------------------------------------
#define S2_STAGEF 8192                    // floats per stage: A 4096 + B 4096
#define S2_SMEM (4 * S2_STAGEF * 4)       // 131072 B

__global__ void __launch_bounds__(256, 1)
stage2_mma(const float* __restrict__ qtf, const float* __restrict__ Tk,
           const float* __restrict__ score_w, const float* __restrict__ score_b,
           float* __restrict__ other)
{
    extern __shared__ float smf[];
    const int tid = threadIdx.x;
    const int lane = tid & 31;
    const int wid = tid >> 5;
    const int wm = wid >> 2;
    const int wn = wid & 3;
    const int q0 = blockIdx.y * 128;
    const int c0 = blockIdx.x * 128;

    const size_t aBase = (size_t)(q0 >> 7) * 16 * 4096;   // [qblk][t][4096]
    const size_t bBase = (size_t)(c0 >> 7) * 16 * 4096;   // within k slab

    float sacc[4][4][4];
#pragma unroll
    for (int mi = 0; mi < 4; mi++)
#pragma unroll
        for (int ni = 0; ni < 4; ni++)
#pragma unroll
            for (int r = 0; r < 4; r++) sacc[mi][ni][r] = 0.0f;

    // issue one chunk load (global chunk index it = k*16 + t)
    auto issue = [&](int it) {
        const int k = it >> 4, t = it & 15, s = it & 3;
        const float* srcA = qtf + aBase + (size_t)t * 4096 + tid * 4;
        const float* srcB = Tk + ((size_t)k << 21) + bBase + (size_t)t * 4096 + tid * 4;
        uint32_t da = smem_u32(smf + s * S2_STAGEF + tid * 4);
        uint32_t db = da + 4096 * 4;
#pragma unroll
        for (int i = 0; i < 4; i++) {
            asm volatile("cp.async.cg.shared.global [%0], [%1], 16;"
                         :: "r"(da + i * 4096), "l"(srcA + i * 1024));
            asm volatile("cp.async.cg.shared.global [%0], [%1], 16;"
                         :: "r"(db + i * 4096), "l"(srcB + i * 1024));
        }
        asm volatile("cp.async.commit_group;" ::: "memory");
    };

    issue(0); issue(1); issue(2);

    float macc[4][4][4];
#pragma unroll 1
    for (int it = 0; it < 128; it++) {
        const int k = it >> 4, t = it & 15, s = it & 3;
        if (t == 0) {
#pragma unroll
            for (int mi = 0; mi < 4; mi++)
#pragma unroll
                for (int ni = 0; ni < 4; ni++)
#pragma unroll
                    for (int r = 0; r < 4; r++) macc[mi][ni][r] = 0.0f;
        }

        if (it < 126)      asm volatile("cp.async.wait_group 2;" ::: "memory");
        else if (it == 126) asm volatile("cp.async.wait_group 1;" ::: "memory");
        else                asm volatile("cp.async.wait_group 0;" ::: "memory");
        __syncthreads();

        if (it + 3 < 128) issue(it + 3);

        const float* pa = smf + s * S2_STAGEF;
        const float* pb = pa + 4096;
#pragma unroll
        for (int d8 = 0; d8 < 4; d8++) {
            float4 a[4];
            float2 b[4];
#pragma unroll
            for (int mi = 0; mi < 4; mi++)
                a[mi] = *(const float4*)(pa + (((wm * 4 + mi) * 4 + d8) << 7) + lane * 4);
#pragma unroll
            for (int ni = 0; ni < 4; ni++)
                b[ni] = *(const float2*)(pb + (((wn * 4 + ni) * 4 + d8) << 6) + lane * 2);
#pragma unroll
            for (int mi = 0; mi < 4; mi++)
#pragma unroll
                for (int ni = 0; ni < 4; ni++)
                    mma_tf32(macc[mi][ni], (const float*)&a[mi], (const float*)&b[ni]);
        }

        if (t == 15) {
            const float w = __ldg(score_w + k);
#pragma unroll
            for (int mi = 0; mi < 4; mi++)
#pragma unroll
                for (int ni = 0; ni < 4; ni++)
#pragma unroll
                    for (int r = 0; r < 4; r++)
                        sacc[mi][ni][r] = fmaf(fmaxf(macc[mi][ni][r], 0.0f), w,
                                               sacc[mi][ni][r]);
        }
    }

    const int lq = lane >> 2;
    const int ld = lane & 3;
    const float sb = __ldg(score_b);
#pragma unroll
    for (int mi = 0; mi < 4; mi++) {
        const int q = q0 + wm * 64 + mi * 16 + lq;
#pragma unroll
        for (int ni = 0; ni < 4; ni++) {
            const int c = c0 + wn * 32 + ni * 8 + 2 * ld;
            float2 v0 = make_float2(sb + sacc[mi][ni][0], sb + sacc[mi][ni][1]);
            float2 v1 = make_float2(sb + sacc[mi][ni][2], sb + sacc[mi][ni][3]);
            *(float2*)(other + (size_t)q * 4096 + c) = v0;
            *(float2*)(other + (size_t)(q + 8) * 4096 + c) = v1;
        }
    }
}

// ---------------------------------------------------------------------------
__global__ void softmax_rows(float* __restrict__ o)
{
    const int row = blockIdx.x;
    float* p = o + (size_t)row * 4096;
    const int tid = threadIdx.x;

    float v[16];
    float mx = -1e30f;
#pragma unroll
    for (int i = 0; i < 16; i++) {
        v[i] = p[tid + (i << 8)];
        mx = fmaxf(mx, v[i]);
    }
    __shared__ float sm[8];
#pragma unroll
    for (int o2 = 16; o2 > 0; o2 >>= 1)
        mx = fmaxf(mx, __shfl_xor_sync(0xffffffffu, mx, o2));
    if ((tid & 31) == 0) sm[tid >> 5] = mx;
    __syncthreads();
    mx = sm[0];
#pragma unroll
    for (int i = 1; i < 8; i++) mx = fmaxf(mx, sm[i]);
    __syncthreads();

    float s = 0.0f;
#pragma unroll
    for (int i = 0; i < 16; i++) { v[i] = expf(v[i] - mx); s += v[i]; }
#pragma unroll
    for (int o2 = 16; o2 > 0; o2 >>= 1)
        s += __shfl_xor_sync(0xffffffffu, s, o2);
    if ((tid & 31) == 0) sm[tid >> 5] = s;
    __syncthreads();
    s = 0.0f;
#pragma unroll
    for (int i = 0; i < 8; i++) s += sm[i];
    float inv = 1.0f / s;
#pragma unroll
    for (int i = 0; i < 16; i++) p[tid + (i << 8)] = v[i] * inv;
}

// ---------------------------------------------------------------------------
// Prep kernels
// ---------------------------------------------------------------------------
__global__ void transpose_hw(const float* __restrict__ hw)
{
    int idx = blockIdx.x * blockDim.x + threadIdx.x;
    int l = idx >> 9;
    int d = idx & 511;
    g_hwT[d * 64 + l] = hw[idx];
}

// query [4096][512] -> g_qtf A-frag packed, tf32-rounded
__global__ void round_query(const float* __restrict__ q)
{
    int idx = blockIdx.x * blockDim.x + threadIdx.x;   // 0..2097151
    int qblk = idx >> 16;
    int rem = idx & 65535;
    int dchunk = rem >> 12;
    int rem2 = rem & 4095;
    int frag = rem2 >> 7;        // r16*4 + d8
    int pos = rem2 & 127;
    int lane = pos >> 2, j = pos & 3;
    int lq = lane >> 2, ld = lane & 3;
    int qq = qblk * 128 + (frag >> 2) * 16 + lq + ((j & 1) << 3);
    int dd = (dchunk << 5) + ((frag & 3) << 3) + ld + ((j >> 1) << 2);
    g_qtf[idx] = tf32r(q[(size_t)qq * 512 + dd]);
}

// in [R][C] (R=k-dim, C=n-dim) -> fragment-packed B hi/lo with Ktot=R
__global__ void transpose_split(const float* __restrict__ in,
                                float* __restrict__ ohi, float* __restrict__ olo,
                                int R, int C)
{
    size_t idx = (size_t)blockIdx.x * blockDim.x + threadIdx.x;
    if (idx >= (size_t)R * C) return;
    int r = (int)(idx / C);
    int c = (int)(idx - (size_t)r * C);
    float v = in[idx];
    float hi = tf32r(v);
    size_t po = bpack_off(c, r, R);
    ohi[po] = hi;
    olo[po] = tf32r(v - hi);
}

// qf = query + sum_z qfp[z]
__global__ void reduce_qf(const float* __restrict__ query)
{
    size_t idx = (size_t)blockIdx.x * blockDim.x + threadIdx.x;
    const size_t S = (size_t)4096 * 512;
    g_qf[idx] = query[idx] + g_qfp[idx] + g_qfp[idx + S] +
                g_qfp[idx + 2 * S] + g_qfp[idx + 3 * S];
}

// ---------------------------------------------------------------------------
extern "C" void kernel_launch(void* const* d_in, const int* in_sizes, int n_in,
                              void* d_out, int out_size)
{
    const float* class_v = (const float*)d_in[0];
    const float* query_v = (const float*)d_in[1];
    const float* Mmat    = (const float*)d_in[2];
    const float* score_w = (const float*)d_in[3];
    const float* score_b = (const float*)d_in[4];
    const float* hash_w  = (const float*)d_in[5];
    const float* hash_b  = (const float*)d_in[6];
    float* out = (float*)d_out;

    float *T, *other, *qf, *hwT, *qtf, *mth, *mtl, *cth, *ctl, *qfp;
    cudaGetSymbolAddress((void**)&T, g_T);
    cudaGetSymbolAddress((void**)&other, g_other);
    cudaGetSymbolAddress((void**)&qf, g_qf);
    cudaGetSymbolAddress((void**)&hwT, g_hwT);
    cudaGetSymbolAddress((void**)&qtf, g_qtf);
    cudaGetSymbolAddress((void**)&mth, g_MT_hi);
    cudaGetSymbolAddress((void**)&mtl, g_MT_lo);
    cudaGetSymbolAddress((void**)&cth, g_clT_hi);
    cudaGetSymbolAddress((void**)&ctl, g_clT_lo);
    cudaGetSymbolAddress((void**)&qfp, g_qfp);

    cudaFuncSetAttribute(stage2_mma, cudaFuncAttributeMaxDynamicSharedMemorySize, S2_SMEM);
    cudaFuncSetAttribute(gemm3x<0>, cudaFuncAttributeMaxDynamicSharedMemorySize, G3_SMEM);
    cudaFuncSetAttribute(gemm3x<1>, cudaFuncAttributeMaxDynamicSharedMemorySize, G3_SMEM);

    // prep
    transpose_hw<<<128, 256>>>(hash_w);
    round_query<<<8192, 256>>>(query_v);
    transpose_split<<<8192, 256>>>(Mmat, mth, mtl, 512, 4096);     // M^T packed
    transpose_split<<<8192, 256>>>(class_v, cth, ctl, 4096, 512);  // class^T packed

    // Stage 1: Tk = class @ M (3xTF32, packed-scatter epilogue)
    gemm3x<0><<<dim3(32, 32, 1), 256, G3_SMEM>>>(class_v, mth, mtl, T, 512, 512, 512);

    // Stage 2: fused bilinear + relu + score (frag-packed tf32 mma)
    stage2_mma<<<dim3(32, 32), 256, S2_SMEM>>>(qtf, T, score_w, score_b, other);

    // Stage 3: softmax
    softmax_rows<<<4096, 256>>>(other);

    // Stage 4: qf partials (3xTF32, split-K=4) + reduce with residual
    gemm3x<1><<<dim3(4, 32, 4), 256, G3_SMEM>>>(other, cth, ctl, qfp, 4096, 4096, 1024);
    reduce_qf<<<8192, 256>>>(query_v);

    // Stage 5: out = tanh(qf @ hwT + hash_b)
    gemm_f32<64, 64, 16, 4, 4, 2><<<dim3(1, 64), 256>>>(
        qf, hwT, hash_b, out, 4096, 64, 512);
}

// round 9
// speedup vs baseline: 1.3455x; 1.1354x over previous
#include <cuda_runtime.h>
#include <math.h>
#include <stdint.h>

// ---------------------------------------------------------------------------
// Dims: D=512, K=8, L=64, Q=4096, C=4096
//   Tk (B-frag packed) = class @ M          (3xTF32 mma, A pre-split)
//   other[q,c] = b + sum_k w_k*relu(q.Tk)   (tf32 mma, frag-packed, 64-d chunks)
//   sc         = softmax_rows(other)        (written A-frag packed, tf32)
//   qf         = sc @ class + query         (2xTF32 mma: A single, B split; splitK=4)
//   out        = tanh(qf @ hash_w^T + b)    (SIMT GEMM)
// Target sm_103 (no 'a'): mma.sync/cp.async only.
//
// Fragment packing (m16n8k8 tf32 row.col), lane L: lq=L>>2, ld=L&3.
//  A-frag (16m x 8k): 128 floats; L*4+j: j -> (m̂=lq+8*(j&1), k̂=ld+4*(j>>1))
//  B-frag (8n x 8k):   64 floats; L*2+s: s -> (n̂=lq, k̂=ld+4*s)
//  A chunk (128m x 32k) = 32 frags (r16*4+k8)*128 = 16KB contiguous
//  B chunk (128n x 32k) = 64 frags (nf*4+k8)*64   = 16KB contiguous
// ---------------------------------------------------------------------------

__device__ float g_T[(size_t)8 * 4096 * 512];    // Tk B-frag packed per k slab
__device__ float g_other[(size_t)4096 * 4096];   // stage2 logits (row-major)
__device__ float g_sc[(size_t)4096 * 4096];      // scores, A-frag packed tf32
__device__ float g_qf[(size_t)4096 * 512];
__device__ float g_qtf[(size_t)4096 * 512];      // query, A-frag packed tf32
__device__ float g_hwT[512 * 64];
__device__ float g_MT_hi[(size_t)4096 * 512];    // M^T B-packed hi/lo
__device__ float g_MT_lo[(size_t)4096 * 512];
__device__ float g_clT_hi[(size_t)512 * 4096];   // class^T B-packed hi/lo
__device__ float g_clT_lo[(size_t)512 * 4096];
__device__ float g_clA_hi[(size_t)4096 * 512];   // class A-packed hi/lo
__device__ float g_clA_lo[(size_t)4096 * 512];
__device__ float g_qfp[(size_t)4 * 4096 * 512];  // split-K partials

// ------------------------------ helpers -----------------------------------
__device__ __forceinline__ uint32_t smem_u32(const void* p) {
    uint32_t a;
    asm("{ .reg .u64 t; cvta.to.shared.u64 t, %1; cvt.u32.u64 %0, t; }" : "=r"(a) : "l"(p));
    return a;
}
__device__ __forceinline__ float tf32r(float x) {
    unsigned u;
    asm("cvt.rna.tf32.f32 %0, %1;" : "=r"(u) : "f"(x));
    return __uint_as_float(u);
}
__device__ __forceinline__ void mma_tf32(float* c, const float* a, const float* b) {
    asm volatile(
        "mma.sync.aligned.m16n8k8.row.col.f32.tf32.tf32.f32 "
        "{%0,%1,%2,%3}, {%4,%5,%6,%7}, {%8,%9}, {%0,%1,%2,%3};"
        : "+f"(c[0]), "+f"(c[1]), "+f"(c[2]), "+f"(c[3])
        : "r"(__float_as_uint(a[0])), "r"(__float_as_uint(a[1])),
          "r"(__float_as_uint(a[2])), "r"(__float_as_uint(a[3])),
          "r"(__float_as_uint(b[0])), "r"(__float_as_uint(b[1])));
}
// packed-B offset for element (n, k), reduction length Ktot
__device__ __forceinline__ size_t bpack_off(int n, int k, int Ktot) {
    return ((size_t)(n >> 7) * (Ktot >> 5) + (k >> 5)) * 4096
         + ((((n >> 3) & 15) << 2) + ((k >> 3) & 3)) * 64
         + (((n & 7) << 2) + (k & 3)) * 2 + ((k >> 2) & 1);
}

// ---------------------------------------------------------------------------
// SIMT GEMM for stage 5. EPI 2: tanh(acc + X[c]).
// ---------------------------------------------------------------------------
template <int BM, int BN, int BK, int TM, int TN, int EPI>
__global__ void __launch_bounds__((BM / TM) * (BN / TN), 2)
gemm_f32(const float* __restrict__ A, const float* __restrict__ B,
         const float* __restrict__ X, float* __restrict__ out,
         int M, int N, int K)
{
    constexpr int THREADS = (BM / TM) * (BN / TN);
    __shared__ float As[BK][BM + 4];
    __shared__ float Bs[BK][BN + 4];

    const int bm = blockIdx.y * BM;
    const int bn = blockIdx.x * BN;
    const int tid = threadIdx.x;
    const int tcol = tid % (BN / TN);
    const int trow = tid / (BN / TN);

    float acc[TM][TN];
#pragma unroll
    for (int i = 0; i < TM; i++)
#pragma unroll
        for (int j = 0; j < TN; j++) acc[i][j] = 0.0f;

    for (int k0 = 0; k0 < K; k0 += BK) {
#pragma unroll
        for (int it = 0; it < (BM * BK / 4) / THREADS; it++) {
            int i = tid + it * THREADS;
            int r = i / (BK / 4);
            int c4 = (i % (BK / 4)) * 4;
            float4 v = *(const float4*)(A + (size_t)(bm + r) * K + k0 + c4);
            As[c4 + 0][r] = v.x; As[c4 + 1][r] = v.y;
            As[c4 + 2][r] = v.z; As[c4 + 3][r] = v.w;
        }
#pragma unroll
        for (int it = 0; it < (BK * BN / 4) / THREADS; it++) {
            int i = tid + it * THREADS;
            int r = i / (BN / 4);
            int c4 = (i % (BN / 4)) * 4;
            *(float4*)&Bs[r][c4] = *(const float4*)(B + (size_t)(k0 + r) * N + bn + c4);
        }
        __syncthreads();

#pragma unroll
        for (int kk = 0; kk < BK; kk++) {
            float af[TM], bf[TN];
#pragma unroll
            for (int i = 0; i < TM; i += 4) {
                float4 v = *(const float4*)&As[kk][trow * TM + i];
                af[i] = v.x; af[i + 1] = v.y; af[i + 2] = v.z; af[i + 3] = v.w;
            }
#pragma unroll
            for (int j = 0; j < TN; j += 4) {
                float4 v = *(const float4*)&Bs[kk][tcol * TN + j];
                bf[j] = v.x; bf[j + 1] = v.y; bf[j + 2] = v.z; bf[j + 3] = v.w;
            }
#pragma unroll
            for (int i = 0; i < TM; i++)
#pragma unroll
                for (int j = 0; j < TN; j++)
                    acc[i][j] = fmaf(af[i], bf[j], acc[i][j]);
        }
        __syncthreads();
    }

#pragma unroll
    for (int i = 0; i < TM; i++) {
        int r = bm + trow * TM + i;
#pragma unroll
        for (int j = 0; j < TN; j++) {
            int c = bn + tcol * TN + j;
            float v = acc[i][j];
            if (EPI == 2) v = tanhf(v + X[c]);
            out[(size_t)r * N + c] = v;
        }
    }
}

// ---------------------------------------------------------------------------
// mma GEMM for stages 1 & 4: out = A @ B^T, both operands fragment-packed.
//   ASPLIT=2: A hi/lo pre-split (3 MMA: ah*bh + al*bh + ah*bl)
//   ASPLIT=1: A single tf32   (2 MMA: a*bh + a*bl)
//   EPI 0: scatter tf32r(v) to Tk B-packed layout (Ktot_out=512)
//   EPI 1: store partial to out + z*4096*512
// CTA 128m x 128n, 8 warps (2x4), 32-k chunks, 3-stage cp.async pipeline.
// ---------------------------------------------------------------------------
template <int ASPLIT, int EPI>
__global__ void __launch_bounds__(256, 1)
gemm_mma(const float* __restrict__ Ahi, const float* __restrict__ Alo,
         const float* __restrict__ Bhi, const float* __restrict__ Blo,
         float* __restrict__ out, int Ktot, int kseg)
{
    extern __shared__ float smf[];
    constexpr int SF = (2 + ASPLIT) * 4096;   // floats per stage

    const int tid = threadIdx.x;
    const int lane = tid & 31;
    const int wid = tid >> 5;
    const int wm = wid >> 2;
    const int wn = wid & 3;
    const int m0 = blockIdx.y * 128;
    const int n0 = blockIdx.x * 128;
    const int kstart = blockIdx.z * kseg;
    const int nchunks = kseg / 32;

    const size_t aBlk = (size_t)(m0 >> 7) * (Ktot >> 5) * 4096;
    const size_t bBlk = (size_t)(n0 >> 7) * (Ktot >> 5) * 4096;

    float macc[4][4][4];
#pragma unroll
    for (int mi = 0; mi < 4; mi++)
#pragma unroll
        for (int ni = 0; ni < 4; ni++)
#pragma unroll
            for (int r = 0; r < 4; r++) macc[mi][ni][r] = 0.0f;

    auto issue = [&](int it, int s) {
        const int kofs = kstart + it * 32;
        const size_t cofs = (size_t)(kofs >> 5) * 4096 + tid * 4;
        uint32_t base = smem_u32(smf + s * SF + tid * 4);
        const float* pAh = Ahi + aBlk + cofs;
#pragma unroll
        for (int i = 0; i < 4; i++)
            asm volatile("cp.async.cg.shared.global [%0], [%1], 16;"
                         :: "r"(base + i * 4096), "l"(pAh + i * 1024));
        if (ASPLIT == 2) {
            const float* pAl = Alo + aBlk + cofs;
#pragma unroll
            for (int i = 0; i < 4; i++)
                asm volatile("cp.async.cg.shared.global [%0], [%1], 16;"
                             :: "r"(base + 16384 + i * 4096), "l"(pAl + i * 1024));
        }
        const float* pBh = Bhi + bBlk + cofs;
        const float* pBl = Blo + bBlk + cofs;
        uint32_t bb = base + ASPLIT * 16384;
#pragma unroll
        for (int i = 0; i < 4; i++) {
            asm volatile("cp.async.cg.shared.global [%0], [%1], 16;"
                         :: "r"(bb + i * 4096), "l"(pBh + i * 1024));
            asm volatile("cp.async.cg.shared.global [%0], [%1], 16;"
                         :: "r"(bb + 16384 + i * 4096), "l"(pBl + i * 1024));
        }
        asm volatile("cp.async.commit_group;" ::: "memory");
    };

    issue(0, 0);
    issue(1, 1);

    int s = 0;
#pragma unroll 1
    for (int it = 0; it < nchunks; it++) {
        if (it < nchunks - 1) asm volatile("cp.async.wait_group 1;" ::: "memory");
        else                  asm volatile("cp.async.wait_group 0;" ::: "memory");
        __syncthreads();
        if (it + 2 < nchunks) {
            int s2 = s + 2; if (s2 >= 3) s2 -= 3;
            issue(it + 2, s2);
        }

        const float* pa = smf + s * SF;
        const float* pal = pa + 4096;
        const float* pbh = pa + ASPLIT * 4096;
        const float* pbl = pbh + 4096;
#pragma unroll
        for (int d8 = 0; d8 < 4; d8++) {
            float4 ah[4], al[4];
            float2 bh[4], bl[4];
#pragma unroll
            for (int mi = 0; mi < 4; mi++) {
                int ao = (((wm * 4 + mi) * 4 + d8) << 7) + lane * 4;
                ah[mi] = *(const float4*)(pa + ao);
                if (ASPLIT == 2) al[mi] = *(const float4*)(pal + ao);
            }
#pragma unroll
            for (int ni = 0; ni < 4; ni++) {
                int bo = (((wn * 4 + ni) * 4 + d8) << 6) + lane * 2;
                bh[ni] = *(const float2*)(pbh + bo);
                bl[ni] = *(const float2*)(pbl + bo);
            }
#pragma unroll
            for (int mi = 0; mi < 4; mi++)
#pragma unroll
                for (int ni = 0; ni < 4; ni++) {
                    mma_tf32(macc[mi][ni], (const float*)&ah[mi], (const float*)&bh[ni]);
                    if (ASPLIT == 2)
                        mma_tf32(macc[mi][ni], (const float*)&al[mi], (const float*)&bh[ni]);
                    mma_tf32(macc[mi][ni], (const float*)&ah[mi], (const float*)&bl[ni]);
                }
        }
        if (++s >= 3) s -= 3;
    }

    const int lq = lane >> 2;
    const int ld = lane & 3;
    if (EPI == 0) {
#pragma unroll
        for (int mi = 0; mi < 4; mi++) {
            const int r = m0 + wm * 64 + mi * 16 + lq;
#pragma unroll
            for (int ni = 0; ni < 4; ni++) {
                const int c = n0 + wn * 32 + ni * 8 + 2 * ld;
#pragma unroll
                for (int rr = 0; rr < 4; rr++) {
                    int row = r + (rr >> 1) * 8;
                    int col = c + (rr & 1);
                    int kp = col & 7, dd = col >> 3;
                    size_t idx = ((size_t)kp << 21) + bpack_off(row, dd, 512);
                    out[idx] = tf32r(macc[mi][ni][rr]);
                }
            }
        }
    } else {
        float* ob = out + (size_t)blockIdx.z * 4096 * 512;
#pragma unroll
        for (int mi = 0; mi < 4; mi++) {
            const int r = m0 + wm * 64 + mi * 16 + lq;
#pragma unroll
            for (int ni = 0; ni < 4; ni++) {
                const int c = n0 + wn * 32 + ni * 8 + 2 * ld;
                *(float2*)(ob + (size_t)r * 512 + c) =
                    make_float2(macc[mi][ni][0], macc[mi][ni][1]);
                *(float2*)(ob + (size_t)(r + 8) * 512 + c) =
                    make_float2(macc[mi][ni][2], macc[mi][ni][3]);
            }
        }
    }
}

// ---------------------------------------------------------------------------
// Stage 2: fused bilinear + relu + score. 64-d chunks, 3-stage pipeline.
// ---------------------------------------------------------------------------
#define S2_STAGEF 16384                   // A 8192 + B 8192 floats
#define S2_SMEM (3 * S2_STAGEF * 4)       // 196608 B

__global__ void __launch_bounds__(256, 1)
stage2_mma(const float* __restrict__ qtf, const float* __restrict__ Tk,
           const float* __restrict__ score_w, const float* __restrict__ score_b,
           float* __restrict__ other)
{
    extern __shared__ float smf[];
    const int tid = threadIdx.x;
    const int lane = tid & 31;
    const int wid = tid >> 5;
    const int wm = wid >> 2;
    const int wn = wid & 3;
    const int q0 = blockIdx.y * 128;
    const int c0 = blockIdx.x * 128;

    const size_t aBase = (size_t)(q0 >> 7) * 65536;
    const size_t bBase = (size_t)(c0 >> 7) * 65536;

    float sacc[4][4][4];
#pragma unroll
    for (int mi = 0; mi < 4; mi++)
#pragma unroll
        for (int ni = 0; ni < 4; ni++)
#pragma unroll
            for (int r = 0; r < 4; r++) sacc[mi][ni][r] = 0.0f;

    // chunk it = k*8 + t64 (64-d chunks)
    auto issue = [&](int it, int s) {
        const int k = it >> 3, t = it & 7;
        const float* srcA = qtf + aBase + (size_t)t * 8192 + tid * 4;
        const float* srcB = Tk + ((size_t)k << 21) + bBase + (size_t)t * 8192 + tid * 4;
        uint32_t da = smem_u32(smf + s * S2_STAGEF + tid * 4);
        uint32_t db = da + 32768;
#pragma unroll
        for (int i = 0; i < 8; i++) {
            asm volatile("cp.async.cg.shared.global [%0], [%1], 16;"
                         :: "r"(da + i * 4096), "l"(srcA + i * 1024));
            asm volatile("cp.async.cg.shared.global [%0], [%1], 16;"
                         :: "r"(db + i * 4096), "l"(srcB + i * 1024));
        }
        asm volatile("cp.async.commit_group;" ::: "memory");
    };

    issue(0, 0);
    issue(1, 1);

    float macc[4][4][4];
    int s = 0;
#pragma unroll 1
    for (int it = 0; it < 64; it++) {
        const int k = it >> 3, t = it & 7;
        if (t == 0) {
#pragma unroll
            for (int mi = 0; mi < 4; mi++)
#pragma unroll
                for (int ni = 0; ni < 4; ni++)
#pragma unroll
                    for (int r = 0; r < 4; r++) macc[mi][ni][r] = 0.0f;
        }

        if (it < 63) asm volatile("cp.async.wait_group 1;" ::: "memory");
        else         asm volatile("cp.async.wait_group 0;" ::: "memory");
        __syncthreads();
        if (it + 2 < 64) {
            int s2 = s + 2; if (s2 >= 3) s2 -= 3;
            issue(it + 2, s2);
        }

        const float* pa = smf + s * S2_STAGEF;
        const float* pb = pa + 8192;
#pragma unroll
        for (int d8 = 0; d8 < 8; d8++) {
            const int half = (d8 >> 2) * 4096;
            const int dd = d8 & 3;
            float4 a[4];
            float2 b[4];
#pragma unroll
            for (int mi = 0; mi < 4; mi++)
                a[mi] = *(const float4*)(pa + half + (((wm * 4 + mi) * 4 + dd) << 7) + lane * 4);
#pragma unroll
            for (int ni = 0; ni < 4; ni++)
                b[ni] = *(const float2*)(pb + half + (((wn * 4 + ni) * 4 + dd) << 6) + lane * 2);
#pragma unroll
            for (int mi = 0; mi < 4; mi++)
#pragma unroll
                for (int ni = 0; ni < 4; ni++)
                    mma_tf32(macc[mi][ni], (const float*)&a[mi], (const float*)&b[ni]);
        }

        if (t == 7) {
            const float w = __ldg(score_w + k);
#pragma unroll
            for (int mi = 0; mi < 4; mi++)
#pragma unroll
                for (int ni = 0; ni < 4; ni++)
#pragma unroll
                    for (int r = 0; r < 4; r++)
                        sacc[mi][ni][r] = fmaf(fmaxf(macc[mi][ni][r], 0.0f), w,
                                               sacc[mi][ni][r]);
        }
        if (++s >= 3) s -= 3;
    }

    const int lq = lane >> 2;
    const int ld = lane & 3;
    const float sb = __ldg(score_b);
#pragma unroll
    for (int mi = 0; mi < 4; mi++) {
        const int q = q0 + wm * 64 + mi * 16 + lq;
#pragma unroll
        for (int ni = 0; ni < 4; ni++) {
            const int c = c0 + wn * 32 + ni * 8 + 2 * ld;
            float2 v0 = make_float2(sb + sacc[mi][ni][0], sb + sacc[mi][ni][1]);
            float2 v1 = make_float2(sb + sacc[mi][ni][2], sb + sacc[mi][ni][3]);
            *(float2*)(other + (size_t)q * 4096 + c) = v0;
            *(float2*)(other + (size_t)(q + 8) * 4096 + c) = v1;
        }
    }
}

// ---------------------------------------------------------------------------
// Softmax over rows; writes scores A-frag packed + tf32-rounded to g_sc.
// ---------------------------------------------------------------------------
__global__ void softmax_pack(const float* __restrict__ o)
{
    const int q = blockIdx.x;
    const float* p = o + (size_t)q * 4096;
    const int tid = threadIdx.x;

    float v[16];
    float mx = -1e30f;
#pragma unroll
    for (int i = 0; i < 16; i++) {
        v[i] = p[tid + (i << 8)];
        mx = fmaxf(mx, v[i]);
    }
    __shared__ float sm[8];
#pragma unroll
    for (int o2 = 16; o2 > 0; o2 >>= 1)
        mx = fmaxf(mx, __shfl_xor_sync(0xffffffffu, mx, o2));
    if ((tid & 31) == 0) sm[tid >> 5] = mx;
    __syncthreads();
    mx = sm[0];
#pragma unroll
    for (int i = 1; i < 8; i++) mx = fmaxf(mx, sm[i]);
    __syncthreads();

    float s = 0.0f;
#pragma unroll
    for (int i = 0; i < 16; i++) { v[i] = expf(v[i] - mx); s += v[i]; }
#pragma unroll
    for (int o2 = 16; o2 > 0; o2 >>= 1)
        s += __shfl_xor_sync(0xffffffffu, s, o2);
    if ((tid & 31) == 0) sm[tid >> 5] = s;
    __syncthreads();
    s = 0.0f;
#pragma unroll
    for (int i = 0; i < 8; i++) s += sm[i];
    const float inv = 1.0f / s;

    // packed write: A-layout with Ktot=4096 (qblk stride 128*4096)
    const size_t qpart = (size_t)(q >> 7) * 524288
                       + (((q >> 4) & 7) * 4) * 128
                       + (q & 7) * 16 + ((q >> 3) & 1);
#pragma unroll
    for (int i = 0; i < 16; i++) {
        int c = tid + (i << 8);
        size_t cpart = (size_t)(c >> 5) * 4096 + ((c >> 3) & 3) * 128
                     + (c & 3) * 4 + ((c >> 2) & 1) * 2;
        g_sc[qpart + cpart] = tf32r(v[i] * inv);
    }
}

// ---------------------------------------------------------------------------
// Prep kernels
// ---------------------------------------------------------------------------
__global__ void transpose_hw(const float* __restrict__ hw)
{
    int idx = blockIdx.x * blockDim.x + threadIdx.x;
    int l = idx >> 9;
    int d = idx & 511;
    g_hwT[d * 64 + l] = hw[idx];
}

// query [4096][512] -> g_qtf A-frag packed, tf32-rounded (Ktot=512)
__global__ void round_query(const float* __restrict__ q)
{
    int idx = blockIdx.x * blockDim.x + threadIdx.x;
    int qblk = idx >> 16;
    int rem = idx & 65535;
    int dchunk = rem >> 12;
    int rem2 = rem & 4095;
    int frag = rem2 >> 7;
    int pos = rem2 & 127;
    int lane = pos >> 2, j = pos & 3;
    int lq = lane >> 2, ld = lane & 3;
    int qq = qblk * 128 + (frag >> 2) * 16 + lq + ((j & 1) << 3);
    int dd = (dchunk << 5) + ((frag & 3) << 3) + ld + ((j >> 1) << 2);
    g_qtf[idx] = tf32r(q[(size_t)qq * 512 + dd]);
}

// class_v [4096][512] -> A-frag packed hi/lo split (Ktot=512)
__global__ void pack_a_split(const float* __restrict__ in,
                             float* __restrict__ ohi, float* __restrict__ olo)
{
    int idx = blockIdx.x * blockDim.x + threadIdx.x;
    int mblk = idx >> 16;
    int rem = idx & 65535;
    int kchunk = rem >> 12;
    int rem2 = rem & 4095;
    int frag = rem2 >> 7;
    int pos = rem2 & 127;
    int lane = pos >> 2, j = pos & 3;
    int lq = lane >> 2, ld = lane & 3;
    int m = mblk * 128 + (frag >> 2) * 16 + lq + ((j & 1) << 3);
    int k = (kchunk << 5) + ((frag & 3) << 3) + ld + ((j >> 1) << 2);
    float v = in[(size_t)m * 512 + k];
    float hi = tf32r(v);
    ohi[idx] = hi;
    olo[idx] = tf32r(v - hi);
}

// in [R][C] (R=k-dim, C=n-dim) -> fragment-packed B hi/lo with Ktot=R
__global__ void transpose_split(const float* __restrict__ in,
                                float* __restrict__ ohi, float* __restrict__ olo,
                                int R, int C)
{
    size_t idx = (size_t)blockIdx.x * blockDim.x + threadIdx.x;
    if (idx >= (size_t)R * C) return;
    int r = (int)(idx / C);
    int c = (int)(idx - (size_t)r * C);
    float v = in[idx];
    float hi = tf32r(v);
    size_t po = bpack_off(c, r, R);
    ohi[po] = hi;
    olo[po] = tf32r(v - hi);
}

// qf = query + sum_z qfp[z]
__global__ void reduce_qf(const float* __restrict__ query)
{
    size_t idx = (size_t)blockIdx.x * blockDim.x + threadIdx.x;
    const size_t S = (size_t)4096 * 512;
    g_qf[idx] = query[idx] + g_qfp[idx] + g_qfp[idx + S] +
                g_qfp[idx + 2 * S] + g_qfp[idx + 3 * S];
}

// ---------------------------------------------------------------------------
extern "C" void kernel_launch(void* const* d_in, const int* in_sizes, int n_in,
                              void* d_out, int out_size)
{
    const float* class_v = (const float*)d_in[0];
    const float* query_v = (const float*)d_in[1];
    const float* Mmat    = (const float*)d_in[2];
    const float* score_w = (const float*)d_in[3];
    const float* score_b = (const float*)d_in[4];
    const float* hash_w  = (const float*)d_in[5];
    const float* hash_b  = (const float*)d_in[6];
    float* out = (float*)d_out;

    float *T, *other, *sc, *qf, *hwT, *qtf, *mth, *mtl, *cth, *ctl, *cah, *cal, *qfp;
    cudaGetSymbolAddress((void**)&T, g_T);
    cudaGetSymbolAddress((void**)&other, g_other);
    cudaGetSymbolAddress((void**)&sc, g_sc);
    cudaGetSymbolAddress((void**)&qf, g_qf);
    cudaGetSymbolAddress((void**)&hwT, g_hwT);
    cudaGetSymbolAddress((void**)&qtf, g_qtf);
    cudaGetSymbolAddress((void**)&mth, g_MT_hi);
    cudaGetSymbolAddress((void**)&mtl, g_MT_lo);
    cudaGetSymbolAddress((void**)&cth, g_clT_hi);
    cudaGetSymbolAddress((void**)&ctl, g_clT_lo);
    cudaGetSymbolAddress((void**)&cah, g_clA_hi);
    cudaGetSymbolAddress((void**)&cal, g_clA_lo);
    cudaGetSymbolAddress((void**)&qfp, g_qfp);

    cudaFuncSetAttribute(stage2_mma, cudaFuncAttributeMaxDynamicSharedMemorySize, S2_SMEM);
    cudaFuncSetAttribute(gemm_mma<2, 0>, cudaFuncAttributeMaxDynamicSharedMemorySize,
                         3 * 4 * 4096 * 4);
    cudaFuncSetAttribute(gemm_mma<1, 1>, cudaFuncAttributeMaxDynamicSharedMemorySize,
                         3 * 3 * 4096 * 4);

    // prep
    transpose_hw<<<128, 256>>>(hash_w);
    round_query<<<8192, 256>>>(query_v);
    pack_a_split<<<8192, 256>>>(class_v, cah, cal);
    transpose_split<<<8192, 256>>>(Mmat, mth, mtl, 512, 4096);
    transpose_split<<<8192, 256>>>(class_v, cth, ctl, 4096, 512);

    // Stage 1: Tk = class @ M (3xTF32, all packed, scatter epilogue)
    gemm_mma<2, 0><<<dim3(32, 32, 1), 256, 3 * 4 * 4096 * 4>>>(
        cah, cal, mth, mtl, T, 512, 512);

    // Stage 2: fused bilinear + relu + score
    stage2_mma<<<dim3(32, 32), 256, S2_SMEM>>>(qtf, T, score_w, score_b, other);

    // Stage 3: softmax -> packed tf32 scores
    softmax_pack<<<4096, 256>>>(other);

    // Stage 4: qf partials = sc @ class (2xTF32, split-K=4) + reduce with residual
    gemm_mma<1, 1><<<dim3(4, 32, 4), 256, 3 * 3 * 4096 * 4>>>(
        sc, nullptr, cth, ctl, qfp, 4096, 1024);
    reduce_qf<<<8192, 256>>>(query_v);

    // Stage 5: out = tanh(qf @ hwT + hash_b)
    gemm_f32<64, 64, 16, 4, 4, 2><<<dim3(1, 64), 256>>>(
        qf, hwT, hash_b, out, 4096, 64, 512);
}

// round 10
// speedup vs baseline: 1.4056x; 1.0447x over previous
#include <cuda_runtime.h>
#include <math.h>
#include <stdint.h>

// ---------------------------------------------------------------------------
// Dims: D=512, K=8, L=64, Q=4096, C=4096
//   Tk (B-frag packed) = class @ M          (3xTF32 mma, A pre-split)
//   other[q,c] = b + sum_k w_k*relu(q.Tk)   (tf32 mma, frag-packed, 64-d chunks)
//   sc         = softmax_rows(other)        (A-frag packed, tf32, paired rows)
//   qfp[z]     = sc @ class  (2xTF32 mma, split-K=8)
//   out        = tanh((query + sum_z qfp) @ hash_w^T + b)   (fused SIMT)
// Target sm_103 (no 'a'): mma.sync/cp.async only.
//
// Fragment packing (m16n8k8 tf32 row.col), lane L: lq=L>>2, ld=L&3.
//  A-frag (16m x 8k): 128 floats; L*4+j: j -> (m̂=lq+8*(j&1), k̂=ld+4*(j>>1))
//  B-frag (8n x 8k):   64 floats; L*2+s: s -> (n̂=lq, k̂=ld+4*s)
//  A chunk (128m x 32k) = 32 frags (r16*4+k8)*128 = 16KB contiguous
//  B chunk (128n x 32k) = 64 frags (nf*4+k8)*64   = 16KB contiguous
// ---------------------------------------------------------------------------

__device__ float g_T[(size_t)8 * 4096 * 512];    // Tk B-frag packed per k slab
__device__ float g_other[(size_t)4096 * 4096];   // stage2 logits (row-major)
__device__ float g_sc[(size_t)4096 * 4096];      // scores, A-frag packed tf32
__device__ float g_qtf[(size_t)4096 * 512];      // query, A-frag packed tf32
__device__ float g_hwT[512 * 64];
__device__ float g_MT_hi[(size_t)4096 * 512];    // M^T B-packed hi/lo
__device__ float g_MT_lo[(size_t)4096 * 512];
__device__ float g_clT_hi[(size_t)512 * 4096];   // class^T B-packed hi/lo
__device__ float g_clT_lo[(size_t)512 * 4096];
__device__ float g_clA_hi[(size_t)4096 * 512];   // class A-packed hi/lo
__device__ float g_clA_lo[(size_t)4096 * 512];
__device__ float g_qfp[(size_t)8 * 4096 * 512];  // split-K partials (64 MB)

// ------------------------------ helpers -----------------------------------
__device__ __forceinline__ uint32_t smem_u32(const void* p) {
    uint32_t a;
    asm("{ .reg .u64 t; cvta.to.shared.u64 t, %1; cvt.u32.u64 %0, t; }" : "=r"(a) : "l"(p));
    return a;
}
__device__ __forceinline__ float tf32r(float x) {
    unsigned u;
    asm("cvt.rna.tf32.f32 %0, %1;" : "=r"(u) : "f"(x));
    return __uint_as_float(u);
}
__device__ __forceinline__ void mma_tf32(float* c, const float* a, const float* b) {
    asm volatile(
        "mma.sync.aligned.m16n8k8.row.col.f32.tf32.tf32.f32 "
        "{%0,%1,%2,%3}, {%4,%5,%6,%7}, {%8,%9}, {%0,%1,%2,%3};"
        : "+f"(c[0]), "+f"(c[1]), "+f"(c[2]), "+f"(c[3])
        : "r"(__float_as_uint(a[0])), "r"(__float_as_uint(a[1])),
          "r"(__float_as_uint(a[2])), "r"(__float_as_uint(a[3])),
          "r"(__float_as_uint(b[0])), "r"(__float_as_uint(b[1])));
}
// packed-B offset for element (n, k), reduction length Ktot
__device__ __forceinline__ size_t bpack_off(int n, int k, int Ktot) {
    return ((size_t)(n >> 7) * (Ktot >> 5) + (k >> 5)) * 4096
         + ((((n >> 3) & 15) << 2) + ((k >> 3) & 3)) * 64
         + (((n & 7) << 2) + (k & 3)) * 2 + ((k >> 2) & 1);
}

// ---------------------------------------------------------------------------
// mma GEMM for stages 1 & 4: out = A @ B^T, both operands fragment-packed.
//   ASPLIT=2: A hi/lo pre-split (3 MMA)   ASPLIT=1: A single tf32 (2 MMA)
//   EPI 0: scatter tf32r(v) to Tk B-packed layout (Ktot_out=512)
//   EPI 1: store partial to out + z*4096*512
// CTA 128m x 128n, 8 warps (2x4), 32-k chunks, 3-stage cp.async pipeline.
// ---------------------------------------------------------------------------
template <int ASPLIT, int EPI>
__global__ void __launch_bounds__(256, 1)
gemm_mma(const float* __restrict__ Ahi, const float* __restrict__ Alo,
         const float* __restrict__ Bhi, const float* __restrict__ Blo,
         float* __restrict__ out, int Ktot, int kseg)
{
    extern __shared__ float smf[];
    constexpr int SF = (2 + ASPLIT) * 4096;

    const int tid = threadIdx.x;
    const int lane = tid & 31;
    const int wid = tid >> 5;
    const int wm = wid >> 2;
    const int wn = wid & 3;
    const int m0 = blockIdx.y * 128;
    const int n0 = blockIdx.x * 128;
    const int kstart = blockIdx.z * kseg;
    const int nchunks = kseg / 32;

    const size_t aBlk = (size_t)(m0 >> 7) * (Ktot >> 5) * 4096;
    const size_t bBlk = (size_t)(n0 >> 7) * (Ktot >> 5) * 4096;

    float macc[4][4][4];
#pragma unroll
    for (int mi = 0; mi < 4; mi++)
#pragma unroll
        for (int ni = 0; ni < 4; ni++)
#pragma unroll
            for (int r = 0; r < 4; r++) macc[mi][ni][r] = 0.0f;

    auto issue = [&](int it, int s) {
        const int kofs = kstart + it * 32;
        const size_t cofs = (size_t)(kofs >> 5) * 4096 + tid * 4;
        uint32_t base = smem_u32(smf + s * SF + tid * 4);
        const float* pAh = Ahi + aBlk + cofs;
#pragma unroll
        for (int i = 0; i < 4; i++)
            asm volatile("cp.async.cg.shared.global [%0], [%1], 16;"
                         :: "r"(base + i * 4096), "l"(pAh + i * 1024));
        if (ASPLIT == 2) {
            const float* pAl = Alo + aBlk + cofs;
#pragma unroll
            for (int i = 0; i < 4; i++)
                asm volatile("cp.async.cg.shared.global [%0], [%1], 16;"
                             :: "r"(base + 16384 + i * 4096), "l"(pAl + i * 1024));
        }
        const float* pBh = Bhi + bBlk + cofs;
        const float* pBl = Blo + bBlk + cofs;
        uint32_t bb = base + ASPLIT * 16384;
#pragma unroll
        for (int i = 0; i < 4; i++) {
            asm volatile("cp.async.cg.shared.global [%0], [%1], 16;"
                         :: "r"(bb + i * 4096), "l"(pBh + i * 1024));
            asm volatile("cp.async.cg.shared.global [%0], [%1], 16;"
                         :: "r"(bb + 16384 + i * 4096), "l"(pBl + i * 1024));
        }
        asm volatile("cp.async.commit_group;" ::: "memory");
    };

    issue(0, 0);
    issue(1, 1);

    int s = 0;
#pragma unroll 1
    for (int it = 0; it < nchunks; it++) {
        if (it < nchunks - 1) asm volatile("cp.async.wait_group 1;" ::: "memory");
        else                  asm volatile("cp.async.wait_group 0;" ::: "memory");
        __syncthreads();
        if (it + 2 < nchunks) {
            int s2 = s + 2; if (s2 >= 3) s2 -= 3;
            issue(it + 2, s2);
        }

        const float* pa = smf + s * SF;
        const float* pal = pa + 4096;
        const float* pbh = pa + ASPLIT * 4096;
        const float* pbl = pbh + 4096;
#pragma unroll
        for (int d8 = 0; d8 < 4; d8++) {
            float4 ah[4], al[4];
            float2 bh[4], bl[4];
#pragma unroll
            for (int mi = 0; mi < 4; mi++) {
                int ao = (((wm * 4 + mi) * 4 + d8) << 7) + lane * 4;
                ah[mi] = *(const float4*)(pa + ao);
                if (ASPLIT == 2) al[mi] = *(const float4*)(pal + ao);
            }
#pragma unroll
            for (int ni = 0; ni < 4; ni++) {
                int bo = (((wn * 4 + ni) * 4 + d8) << 6) + lane * 2;
                bh[ni] = *(const float2*)(pbh + bo);
                bl[ni] = *(const float2*)(pbl + bo);
            }
#pragma unroll
            for (int mi = 0; mi < 4; mi++)
#pragma unroll
                for (int ni = 0; ni < 4; ni++) {
                    mma_tf32(macc[mi][ni], (const float*)&ah[mi], (const float*)&bh[ni]);
                    if (ASPLIT == 2)
                        mma_tf32(macc[mi][ni], (const float*)&al[mi], (const float*)&bh[ni]);
                    mma_tf32(macc[mi][ni], (const float*)&ah[mi], (const float*)&bl[ni]);
                }
        }
        if (++s >= 3) s -= 3;
    }

    const int lq = lane >> 2;
    const int ld = lane & 3;
    if (EPI == 0) {
#pragma unroll
        for (int mi = 0; mi < 4; mi++) {
            const int r = m0 + wm * 64 + mi * 16 + lq;
#pragma unroll
            for (int ni = 0; ni < 4; ni++) {
                const int c = n0 + wn * 32 + ni * 8 + 2 * ld;
#pragma unroll
                for (int rr = 0; rr < 4; rr++) {
                    int row = r + (rr >> 1) * 8;
                    int col = c + (rr & 1);
                    int kp = col & 7, dd = col >> 3;
                    size_t idx = ((size_t)kp << 21) + bpack_off(row, dd, 512);
                    out[idx] = tf32r(macc[mi][ni][rr]);
                }
            }
        }
    } else {
        float* ob = out + (size_t)blockIdx.z * 4096 * 512;
#pragma unroll
        for (int mi = 0; mi < 4; mi++) {
            const int r = m0 + wm * 64 + mi * 16 + lq;
#pragma unroll
            for (int ni = 0; ni < 4; ni++) {
                const int c = n0 + wn * 32 + ni * 8 + 2 * ld;
                *(float2*)(ob + (size_t)r * 512 + c) =
                    make_float2(macc[mi][ni][0], macc[mi][ni][1]);
                *(float2*)(ob + (size_t)(r + 8) * 512 + c) =
                    make_float2(macc[mi][ni][2], macc[mi][ni][3]);
            }
        }
    }
}

// ---------------------------------------------------------------------------
// Stage 2: fused bilinear + relu + score. 64-d chunks, 3-stage pipeline.
// ---------------------------------------------------------------------------
#define S2_STAGEF 16384
#define S2_SMEM (3 * S2_STAGEF * 4)

__global__ void __launch_bounds__(256, 1)
stage2_mma(const float* __restrict__ qtf, const float* __restrict__ Tk,
           const float* __restrict__ score_w, const float* __restrict__ score_b,
           float* __restrict__ other)
{
    extern __shared__ float smf[];
    const int tid = threadIdx.x;
    const int lane = tid & 31;
    const int wid = tid >> 5;
    const int wm = wid >> 2;
    const int wn = wid & 3;
    const int q0 = blockIdx.y * 128;
    const int c0 = blockIdx.x * 128;

    const size_t aBase = (size_t)(q0 >> 7) * 65536;
    const size_t bBase = (size_t)(c0 >> 7) * 65536;

    float sacc[4][4][4];
#pragma unroll
    for (int mi = 0; mi < 4; mi++)
#pragma unroll
        for (int ni = 0; ni < 4; ni++)
#pragma unroll
            for (int r = 0; r < 4; r++) sacc[mi][ni][r] = 0.0f;

    auto issue = [&](int it, int s) {
        const int k = it >> 3, t = it & 7;
        const float* srcA = qtf + aBase + (size_t)t * 8192 + tid * 4;
        const float* srcB = Tk + ((size_t)k << 21) + bBase + (size_t)t * 8192 + tid * 4;
        uint32_t da = smem_u32(smf + s * S2_STAGEF + tid * 4);
        uint32_t db = da + 32768;
#pragma unroll
        for (int i = 0; i < 8; i++) {
            asm volatile("cp.async.cg.shared.global [%0], [%1], 16;"
                         :: "r"(da + i * 4096), "l"(srcA + i * 1024));
            asm volatile("cp.async.cg.shared.global [%0], [%1], 16;"
                         :: "r"(db + i * 4096), "l"(srcB + i * 1024));
        }
        asm volatile("cp.async.commit_group;" ::: "memory");
    };

    issue(0, 0);
    issue(1, 1);

    float macc[4][4][4];
    int s = 0;
#pragma unroll 1
    for (int it = 0; it < 64; it++) {
        const int k = it >> 3, t = it & 7;
        if (t == 0) {
#pragma unroll
            for (int mi = 0; mi < 4; mi++)
#pragma unroll
                for (int ni = 0; ni < 4; ni++)
#pragma unroll
                    for (int r = 0; r < 4; r++) macc[mi][ni][r] = 0.0f;
        }

        if (it < 63) asm volatile("cp.async.wait_group 1;" ::: "memory");
        else         asm volatile("cp.async.wait_group 0;" ::: "memory");
        __syncthreads();
        if (it + 2 < 64) {
            int s2 = s + 2; if (s2 >= 3) s2 -= 3;
            issue(it + 2, s2);
        }

        const float* pa = smf + s * S2_STAGEF;
        const float* pb = pa + 8192;
#pragma unroll
        for (int d8 = 0; d8 < 8; d8++) {
            const int half = (d8 >> 2) * 4096;
            const int dd = d8 & 3;
            float4 a[4];
            float2 b[4];
#pragma unroll
            for (int mi = 0; mi < 4; mi++)
                a[mi] = *(const float4*)(pa + half + (((wm * 4 + mi) * 4 + dd) << 7) + lane * 4);
#pragma unroll
            for (int ni = 0; ni < 4; ni++)
                b[ni] = *(const float2*)(pb + half + (((wn * 4 + ni) * 4 + dd) << 6) + lane * 2);
#pragma unroll
            for (int mi = 0; mi < 4; mi++)
#pragma unroll
                for (int ni = 0; ni < 4; ni++)
                    mma_tf32(macc[mi][ni], (const float*)&a[mi], (const float*)&b[ni]);
        }

        if (t == 7) {
            const float w = __ldg(score_w + k);
#pragma unroll
            for (int mi = 0; mi < 4; mi++)
#pragma unroll
                for (int ni = 0; ni < 4; ni++)
#pragma unroll
                    for (int r = 0; r < 4; r++)
                        sacc[mi][ni][r] = fmaf(fmaxf(macc[mi][ni][r], 0.0f), w,
                                               sacc[mi][ni][r]);
        }
        if (++s >= 3) s -= 3;
    }

    const int lq = lane >> 2;
    const int ld = lane & 3;
    const float sb = __ldg(score_b);
#pragma unroll
    for (int mi = 0; mi < 4; mi++) {
        const int q = q0 + wm * 64 + mi * 16 + lq;
#pragma unroll
        for (int ni = 0; ni < 4; ni++) {
            const int c = c0 + wn * 32 + ni * 8 + 2 * ld;
            float2 v0 = make_float2(sb + sacc[mi][ni][0], sb + sacc[mi][ni][1]);
            float2 v1 = make_float2(sb + sacc[mi][ni][2], sb + sacc[mi][ni][3]);
            *(float2*)(other + (size_t)q * 4096 + c) = v0;
            *(float2*)(other + (size_t)(q + 8) * 4096 + c) = v1;
        }
    }
}

// ---------------------------------------------------------------------------
// Softmax over paired rows (q, q+8); writes A-frag packed tf32 float2
// (the pair's packed elements are adjacent -> fully coalesced sectors).
// ---------------------------------------------------------------------------
__global__ void softmax_pack2(const float* __restrict__ o, float* __restrict__ sc)
{
    const int b = blockIdx.x;                     // 0..2047
    const int qa = ((b >> 3) << 4) | (b & 7);     // bit3 = 0
    const float* p0 = o + (size_t)qa * 4096;
    const float* p1 = p0 + 8 * 4096;
    const int tid = threadIdx.x;

    float v0[16], v1[16];
    float mx0 = -1e30f, mx1 = -1e30f;
#pragma unroll
    for (int i = 0; i < 16; i++) {
        v0[i] = p0[tid + (i << 8)];
        v1[i] = p1[tid + (i << 8)];
        mx0 = fmaxf(mx0, v0[i]);
        mx1 = fmaxf(mx1, v1[i]);
    }
    __shared__ float sm0[8], sm1[8];
#pragma unroll
    for (int o2 = 16; o2 > 0; o2 >>= 1) {
        mx0 = fmaxf(mx0, __shfl_xor_sync(0xffffffffu, mx0, o2));
        mx1 = fmaxf(mx1, __shfl_xor_sync(0xffffffffu, mx1, o2));
    }
    if ((tid & 31) == 0) { sm0[tid >> 5] = mx0; sm1[tid >> 5] = mx1; }
    __syncthreads();
    mx0 = sm0[0]; mx1 = sm1[0];
#pragma unroll
    for (int i = 1; i < 8; i++) { mx0 = fmaxf(mx0, sm0[i]); mx1 = fmaxf(mx1, sm1[i]); }
    __syncthreads();

    float s0 = 0.0f, s1 = 0.0f;
#pragma unroll
    for (int i = 0; i < 16; i++) {
        v0[i] = expf(v0[i] - mx0); s0 += v0[i];
        v1[i] = expf(v1[i] - mx1); s1 += v1[i];
    }
#pragma unroll
    for (int o2 = 16; o2 > 0; o2 >>= 1) {
        s0 += __shfl_xor_sync(0xffffffffu, s0, o2);
        s1 += __shfl_xor_sync(0xffffffffu, s1, o2);
    }
    if ((tid & 31) == 0) { sm0[tid >> 5] = s0; sm1[tid >> 5] = s1; }
    __syncthreads();
    s0 = 0.0f; s1 = 0.0f;
#pragma unroll
    for (int i = 0; i < 8; i++) { s0 += sm0[i]; s1 += sm1[i]; }
    const float i0 = 1.0f / s0, i1 = 1.0f / s1;

    // packed A-layout (Ktot=4096); rows qa (bit=0) and qa+8 (bit=1) adjacent
    const size_t qpart = (size_t)(qa >> 7) * 524288
                       + (((qa >> 4) & 7) << 9) + ((qa & 7) << 4);
#pragma unroll
    for (int i = 0; i < 16; i++) {
        int c = tid + (i << 8);
        size_t cpart = (size_t)(c >> 5) * 4096 + (((c >> 3) & 3) << 7)
                     + ((c & 3) << 2) + (((c >> 2) & 1) << 1);
        *(float2*)(sc + qpart + cpart) =
            make_float2(tf32r(v0[i] * i0), tf32r(v1[i] * i1));
    }
}

// ---------------------------------------------------------------------------
// Fused stage 5: qf = query + sum_z qfp[z] (smem), out = tanh(qf @ hwT + b).
// Block = 16 q rows, 256 threads.
// ---------------------------------------------------------------------------
__global__ void __launch_bounds__(256, 2)
stage5_fused(const float* __restrict__ query, const float* __restrict__ qfp,
             const float* __restrict__ hwT, const float* __restrict__ hash_b,
             float* __restrict__ out)
{
    __shared__ float qf_s[16 * 512];
    const int tid = threadIdx.x;
    const int qbase = blockIdx.x * 16;
    const size_t S = (size_t)4096 * 512;
    const size_t gbase = (size_t)qbase * 512;

    // Phase 1: 2048 float4 = 16 rows x 128 f4
#pragma unroll
    for (int j = 0; j < 8; j++) {
        int i4 = tid + j * 256;
        size_t g = gbase + (size_t)i4 * 4;
        float4 acc = *(const float4*)(query + g);
#pragma unroll
        for (int z = 0; z < 8; z++) {
            float4 p = *(const float4*)(qfp + z * S + g);
            acc.x += p.x; acc.y += p.y; acc.z += p.z; acc.w += p.w;
        }
        *(float4*)(qf_s + i4 * 4) = acc;
    }
    __syncthreads();

    // Phase 2: thread (q = tid>>4, l = (tid&15)*4 .. +3)
    const int q = tid >> 4;
    const int lb = (tid & 15) * 4;
    float a0 = 0, a1 = 0, a2 = 0, a3 = 0;
    const float* qr = qf_s + q * 512;
#pragma unroll 4
    for (int d = 0; d < 512; d += 4) {
        float4 qv = *(const float4*)(qr + d);
        float4 h0 = __ldg((const float4*)(hwT + (size_t)d * 64 + lb));
        float4 h1 = __ldg((const float4*)(hwT + (size_t)(d + 1) * 64 + lb));
        float4 h2 = __ldg((const float4*)(hwT + (size_t)(d + 2) * 64 + lb));
        float4 h3 = __ldg((const float4*)(hwT + (size_t)(d + 3) * 64 + lb));
        a0 = fmaf(qv.x, h0.x, fmaf(qv.y, h1.x, fmaf(qv.z, h2.x, fmaf(qv.w, h3.x, a0))));
        a1 = fmaf(qv.x, h0.y, fmaf(qv.y, h1.y, fmaf(qv.z, h2.y, fmaf(qv.w, h3.y, a1))));
        a2 = fmaf(qv.x, h0.z, fmaf(qv.y, h1.z, fmaf(qv.z, h2.z, fmaf(qv.w, h3.z, a2))));
        a3 = fmaf(qv.x, h0.w, fmaf(qv.y, h1.w, fmaf(qv.z, h2.w, fmaf(qv.w, h3.w, a3))));
    }
    float4 hb = __ldg((const float4*)(hash_b + lb));
    float4 r = make_float4(tanhf(a0 + hb.x), tanhf(a1 + hb.y),
                           tanhf(a2 + hb.z), tanhf(a3 + hb.w));
    *(float4*)(out + (size_t)(qbase + q) * 64 + lb) = r;
}

// ---------------------------------------------------------------------------
// Prep kernels
// ---------------------------------------------------------------------------
__global__ void transpose_hw(const float* __restrict__ hw)
{
    int idx = blockIdx.x * blockDim.x + threadIdx.x;
    int l = idx >> 9;
    int d = idx & 511;
    g_hwT[d * 64 + l] = hw[idx];
}

// query [4096][512] -> g_qtf A-frag packed, tf32-rounded (Ktot=512)
__global__ void round_query(const float* __restrict__ q)
{
    int idx = blockIdx.x * blockDim.x + threadIdx.x;
    int qblk = idx >> 16;
    int rem = idx & 65535;
    int dchunk = rem >> 12;
    int rem2 = rem & 4095;
    int frag = rem2 >> 7;
    int pos = rem2 & 127;
    int lane = pos >> 2, j = pos & 3;
    int lq = lane >> 2, ld = lane & 3;
    int qq = qblk * 128 + (frag >> 2) * 16 + lq + ((j & 1) << 3);
    int dd = (dchunk << 5) + ((frag & 3) << 3) + ld + ((j >> 1) << 2);
    g_qtf[idx] = tf32r(q[(size_t)qq * 512 + dd]);
}

// class_v [4096][512] -> A-frag packed hi/lo split (Ktot=512)
__global__ void pack_a_split(const float* __restrict__ in,
                             float* __restrict__ ohi, float* __restrict__ olo)
{
    int idx = blockIdx.x * blockDim.x + threadIdx.x;
    int mblk = idx >> 16;
    int rem = idx & 65535;
    int kchunk = rem >> 12;
    int rem2 = rem & 4095;
    int frag = rem2 >> 7;
    int pos = rem2 & 127;
    int lane = pos >> 2, j = pos & 3;
    int lq = lane >> 2, ld = lane & 3;
    int m = mblk * 128 + (frag >> 2) * 16 + lq + ((j & 1) << 3);
    int k = (kchunk << 5) + ((frag & 3) << 3) + ld + ((j >> 1) << 2);
    float v = in[(size_t)m * 512 + k];
    float hi = tf32r(v);
    ohi[idx] = hi;
    olo[idx] = tf32r(v - hi);
}

// in [R][C] (R=k-dim, C=n-dim) -> fragment-packed B hi/lo with Ktot=R.
// One thread produces one 8-k group (32B contiguous) per output array:
// fully coalesced STG.128 x2 per array; reads coalesced along n.
__global__ void transpose_split(const float* __restrict__ in,
                                float* __restrict__ ohi, float* __restrict__ olo,
                                int R, int C)
{
    unsigned t = blockIdx.x * blockDim.x + threadIdx.x;   // C * R/8 threads
    unsigned k8 = t / (unsigned)C;
    unsigned n = t - k8 * (unsigned)C;
    int kb = (int)k8 * 8;

    float h[8], l[8];
#pragma unroll
    for (int i = 0; i < 8; i++) {
        float v = in[(size_t)(kb + i) * C + n];
        h[i] = tf32r(v);
        l[i] = tf32r(v - h[i]);
    }
    // within-group order: pos o holds k = (o&1)*4 + (o>>1)
    size_t base = bpack_off((int)n, kb, R);   // low 3 bits zero
    *(float4*)(ohi + base)     = make_float4(h[0], h[4], h[1], h[5]);
    *(float4*)(ohi + base + 4) = make_float4(h[2], h[6], h[3], h[7]);
    *(float4*)(olo + base)     = make_float4(l[0], l[4], l[1], l[5]);
    *(float4*)(olo + base + 4) = make_float4(l[2], l[6], l[3], l[7]);
}

// ---------------------------------------------------------------------------
extern "C" void kernel_launch(void* const* d_in, const int* in_sizes, int n_in,
                              void* d_out, int out_size)
{
    const float* class_v = (const float*)d_in[0];
    const float* query_v = (const float*)d_in[1];
    const float* Mmat    = (const float*)d_in[2];
    const float* score_w = (const float*)d_in[3];
    const float* score_b = (const float*)d_in[4];
    const float* hash_w  = (const float*)d_in[5];
    const float* hash_b  = (const float*)d_in[6];
    float* out = (float*)d_out;

    float *T, *other, *sc, *hwT, *qtf, *mth, *mtl, *cth, *ctl, *cah, *cal, *qfp;
    cudaGetSymbolAddress((void**)&T, g_T);
    cudaGetSymbolAddress((void**)&other, g_other);
    cudaGetSymbolAddress((void**)&sc, g_sc);
    cudaGetSymbolAddress((void**)&hwT, g_hwT);
    cudaGetSymbolAddress((void**)&qtf, g_qtf);
    cudaGetSymbolAddress((void**)&mth, g_MT_hi);
    cudaGetSymbolAddress((void**)&mtl, g_MT_lo);
    cudaGetSymbolAddress((void**)&cth, g_clT_hi);
    cudaGetSymbolAddress((void**)&ctl, g_clT_lo);
    cudaGetSymbolAddress((void**)&cah, g_clA_hi);
    cudaGetSymbolAddress((void**)&cal, g_clA_lo);
    cudaGetSymbolAddress((void**)&qfp, g_qfp);

    cudaFuncSetAttribute(stage2_mma, cudaFuncAttributeMaxDynamicSharedMemorySize, S2_SMEM);
    cudaFuncSetAttribute(gemm_mma<2, 0>, cudaFuncAttributeMaxDynamicSharedMemorySize,
                         3 * 4 * 4096 * 4);
    cudaFuncSetAttribute(gemm_mma<1, 1>, cudaFuncAttributeMaxDynamicSharedMemorySize,
                         3 * 3 * 4096 * 4);

    // prep
    transpose_hw<<<128, 256>>>(hash_w);
    round_query<<<8192, 256>>>(query_v);
    pack_a_split<<<8192, 256>>>(class_v, cah, cal);
    transpose_split<<<1024, 256>>>(Mmat, mth, mtl, 512, 4096);
    transpose_split<<<1024, 256>>>(class_v, cth, ctl, 4096, 512);

    // Stage 1: Tk = class @ M (3xTF32, all packed, scatter epilogue)
    gemm_mma<2, 0><<<dim3(32, 32, 1), 256, 3 * 4 * 4096 * 4>>>(
        cah, cal, mth, mtl, T, 512, 512);

    // Stage 2: fused bilinear + relu + score
    stage2_mma<<<dim3(32, 32), 256, S2_SMEM>>>(qtf, T, score_w, score_b, other);

    // Stage 3: softmax (paired rows) -> packed tf32 scores
    softmax_pack2<<<2048, 256>>>(other, sc);

    // Stage 4: qf partials = sc @ class (2xTF32, split-K=8)
    gemm_mma<1, 1><<<dim3(4, 32, 8), 256, 3 * 3 * 4096 * 4>>>(
        sc, nullptr, cth, ctl, qfp, 4096, 512);

    // Stage 5 (fused reduce + residual + tanh GEMM)
    stage5_fused<<<256, 256>>>(query_v, qfp, hwT, hash_b, out);
}

// round 11
// speedup vs baseline: 2.5117x; 1.7869x over previous
#include <cuda_runtime.h>
#include <cuda_fp16.h>
#include <math.h>
#include <stdint.h>

// ---------------------------------------------------------------------------
// Dims: D=512, K=8, L=64, Q=4096, C=4096.  All GEMMs on fp16 m16n8k16 mma
// (fp16 mantissa == tf32 mantissa; power-of-2 scaling keeps everything exact).
//   T (B-pack fp16, x2^8)  = class @ M        (3-MMA hi/lo split, ~2^-22)
//   other[q,c] = b + sum_k w_k*relu(q.Tk)     (1 MMA/k16, two-sided 2^-11)
//   sc  = softmax_rows(other)                 (A-pack fp16, x2^6)
//   qfp[z] = sc @ class                       (1 MMA/k16, split-K=8)
//   out = tanh((query + sum_z qfp) @ hash_w^T + b)   (fused SIMT)
// Target sm_103 (no 'a'): mma.sync/cp.async only.
//
// fp16 fragment packing (m16n8k16 row.col), lane L: g=L>>2, t=L&3.
//  A-frag (16m x 16k): 256 halves; lane offset L*8 (16B -> LDS.128);
//    half (r,h): m = g + 8*(r&1), k = t*2 + h + 8*(r>>1)
//  B-frag (8n x 16k): 128 halves; lane offset L*4 (8B -> LDS.64);
//    half (r,h): n = g, k = t*2 + h + 8*r
//  64-k chunks: A chunk (128m x 64k) = 32 frags*256 = 8192 halves (16KB)
//               B chunk (128n x 64k) = 64 frags*128 = 8192 halves (16KB)
// ---------------------------------------------------------------------------

__device__ __half g_T16[(size_t)8 * 4096 * 512];   // T, B-pack, x2^8 (32MB)
__device__ float  g_other[(size_t)4096 * 4096];    // logits fp32 (64MB)
__device__ __half g_sc16[(size_t)4096 * 4096];     // scores A-pack x2^6 (32MB)
__device__ __half g_q16[(size_t)4096 * 512];       // query A-pack x2^8
__device__ __half g_cah[(size_t)4096 * 512];       // class A-pack hi (x2^8)
__device__ __half g_cal[(size_t)4096 * 512];       // class A-pack lo
__device__ __half g_mbh[(size_t)4096 * 512];       // M^T B-pack hi (x2^10)
__device__ __half g_mbl[(size_t)4096 * 512];       // M^T B-pack lo
__device__ __half g_cbh[(size_t)512 * 4096];       // class^T B-pack (x2^8)
__device__ float  g_qfp[(size_t)8 * 4096 * 512];   // split-K partials (64MB)
__device__ float  g_hwT[512 * 64];

// ------------------------------ helpers -----------------------------------
__device__ __forceinline__ uint32_t smem_u32(const void* p) {
    uint32_t a;
    asm("{ .reg .u64 t; cvta.to.shared.u64 t, %1; cvt.u32.u64 %0, t; }" : "=r"(a) : "l"(p));
    return a;
}
__device__ __forceinline__ void mma_f16(float* c, const uint32_t* a, const uint32_t* b) {
    asm volatile(
        "mma.sync.aligned.m16n8k16.row.col.f32.f16.f16.f32 "
        "{%0,%1,%2,%3}, {%4,%5,%6,%7}, {%8,%9}, {%0,%1,%2,%3};"
        : "+f"(c[0]), "+f"(c[1]), "+f"(c[2]), "+f"(c[3])
        : "r"(a[0]), "r"(a[1]), "r"(a[2]), "r"(a[3]), "r"(b[0]), "r"(b[1]));
}
// packed offsets (64-k chunk granularity), element (m|n, k), reduction Ktot
__device__ __forceinline__ size_t apack16(int m, int k, int Ktot) {
    return ((size_t)(m >> 7) * (Ktot >> 6) + (k >> 6)) * 8192
         + (size_t)(((((m >> 4) & 7) << 2) + ((k >> 4) & 3)) * 256
         + (((m & 7) << 2) + ((k & 7) >> 1)) * 8
         + (((k >> 3) & 1) << 2) + (((m >> 3) & 1) << 1) + (k & 1));
}
__device__ __forceinline__ size_t bpack16(int n, int k, int Ktot) {
    return ((size_t)(n >> 7) * (Ktot >> 6) + (k >> 6)) * 8192
         + (size_t)(((((n >> 3) & 15) << 2) + ((k >> 4) & 3)) * 128
         + (((n & 7) << 2) + ((k & 7) >> 1)) * 4
         + (((k >> 3) & 1) << 1) + (k & 1));
}

// ---------------------------------------------------------------------------
// fp16 mma GEMM (stages 1 & 4): out = A @ B^T, operands fragment-packed.
//   SPLIT=1: A,B hi/lo (3 MMA/k16, ~2^-22)   SPLIT=0: single (1 MMA/k16)
//   EPI 0: scatter fp16(acc*2^-10) to T16 B-pack (Ktot_out=512)
//   EPI 1: store fp32 acc*2^-14 partial to out + z*4096*512
// CTA 128m x 128n, 8 warps (2x4), 64-k chunks, 3-stage cp.async pipeline.
// ---------------------------------------------------------------------------
template <int SPLIT, int EPI>
__global__ void __launch_bounds__(256, 1)
gemm_f16(const __half* __restrict__ Ah, const __half* __restrict__ Al,
         const __half* __restrict__ Bh, const __half* __restrict__ Bl,
         float* __restrict__ out, __half* __restrict__ outh,
         int Ktot, int kseg)
{
    extern __shared__ char smc[];
    __half* sm = (__half*)smc;
    constexpr int SF = (SPLIT ? 4 : 2) * 8192;   // halves per stage

    const int tid = threadIdx.x;
    const int lane = tid & 31;
    const int wid = tid >> 5;
    const int wm = wid >> 2;
    const int wn = wid & 3;
    const int m0 = blockIdx.y * 128;
    const int n0 = blockIdx.x * 128;
    const int kstart = blockIdx.z * kseg;
    const int nchunks = kseg / 64;

    const size_t aBlk = ((size_t)(m0 >> 7) * (Ktot >> 6) + (kstart >> 6)) * 8192;
    const size_t bBlk = ((size_t)(n0 >> 7) * (Ktot >> 6) + (kstart >> 6)) * 8192;

    float macc[4][4][4];
#pragma unroll
    for (int mi = 0; mi < 4; mi++)
#pragma unroll
        for (int ni = 0; ni < 4; ni++)
#pragma unroll
            for (int r = 0; r < 4; r++) macc[mi][ni][r] = 0.0f;

    auto issue = [&](int it, int s) {
        const size_t cofs = (size_t)it * 8192 + tid * 8;
        uint32_t base = smem_u32(sm + s * SF) + tid * 16;
#pragma unroll
        for (int i = 0; i < 4; i++)
            asm volatile("cp.async.cg.shared.global [%0], [%1], 16;"
                         :: "r"(base + i * 4096), "l"(Ah + aBlk + cofs + i * 2048));
        if (SPLIT) {
#pragma unroll
            for (int i = 0; i < 4; i++)
                asm volatile("cp.async.cg.shared.global [%0], [%1], 16;"
                             :: "r"(base + 16384 + i * 4096), "l"(Al + aBlk + cofs + i * 2048));
        }
        uint32_t bb = base + (SPLIT ? 32768 : 16384);
#pragma unroll
        for (int i = 0; i < 4; i++)
            asm volatile("cp.async.cg.shared.global [%0], [%1], 16;"
                         :: "r"(bb + i * 4096), "l"(Bh + bBlk + cofs + i * 2048));
        if (SPLIT) {
#pragma unroll
            for (int i = 0; i < 4; i++)
                asm volatile("cp.async.cg.shared.global [%0], [%1], 16;"
                             :: "r"(bb + 16384 + i * 4096), "l"(Bl + bBlk + cofs + i * 2048));
        }
        asm volatile("cp.async.commit_group;" ::: "memory");
    };

    issue(0, 0);
    issue(1, 1);

    int s = 0;
#pragma unroll 1
    for (int it = 0; it < nchunks; it++) {
        if (it < nchunks - 1) asm volatile("cp.async.wait_group 1;" ::: "memory");
        else                  asm volatile("cp.async.wait_group 0;" ::: "memory");
        __syncthreads();
        if (it + 2 < nchunks) {
            int s2 = s + 2; if (s2 >= 3) s2 -= 3;
            issue(it + 2, s2);
        }

        const __half* pa  = sm + s * SF;
        const __half* pal = pa + 8192;
        const __half* pbh = pa + (SPLIT ? 16384 : 8192);
        const __half* pbl = pbh + 8192;
#pragma unroll
        for (int kk = 0; kk < 4; kk++) {
            uint4 ah[4], al[4];
            uint2 bh[4], bl[4];
#pragma unroll
            for (int mi = 0; mi < 4; mi++) {
                int ao = (((wm * 4 + mi) * 4 + kk) << 8) + lane * 8;
                ah[mi] = *(const uint4*)(pa + ao);
                if (SPLIT) al[mi] = *(const uint4*)(pal + ao);
            }
#pragma unroll
            for (int ni = 0; ni < 4; ni++) {
                int bo = (((wn * 4 + ni) * 4 + kk) << 7) + lane * 4;
                bh[ni] = *(const uint2*)(pbh + bo);
                if (SPLIT) bl[ni] = *(const uint2*)(pbl + bo);
            }
#pragma unroll
            for (int mi = 0; mi < 4; mi++)
#pragma unroll
                for (int ni = 0; ni < 4; ni++) {
                    mma_f16(macc[mi][ni], (const uint32_t*)&ah[mi], (const uint32_t*)&bh[ni]);
                    if (SPLIT) {
                        mma_f16(macc[mi][ni], (const uint32_t*)&al[mi], (const uint32_t*)&bh[ni]);
                        mma_f16(macc[mi][ni], (const uint32_t*)&ah[mi], (const uint32_t*)&bl[ni]);
                    }
                }
        }
        if (++s >= 3) s -= 3;
    }

    const int lq = lane >> 2;
    const int ld = lane & 3;
    if (EPI == 0) {
        // scale: A x2^8 * B x2^10 = acc x2^18; want T x2^8 -> *2^-10
        const float ds = 0.0009765625f;
#pragma unroll
        for (int mi = 0; mi < 4; mi++) {
            const int r = m0 + wm * 64 + mi * 16 + lq;
#pragma unroll
            for (int ni = 0; ni < 4; ni++) {
                const int c = n0 + wn * 32 + ni * 8 + 2 * ld;
#pragma unroll
                for (int rr = 0; rr < 4; rr++) {
                    int row = r + (rr >> 1) * 8;
                    int col = c + (rr & 1);
                    int kp = col & 7, dd = col >> 3;
                    outh[(size_t)kp * 2097152 + bpack16(row, dd, 512)] =
                        __float2half_rn(macc[mi][ni][rr] * ds);
                }
            }
        }
    } else {
        // scale: sc x2^6 * class x2^8 = acc x2^14 -> *2^-14
        const float ds = 6.103515625e-05f;
        float* ob = out + (size_t)blockIdx.z * 4096 * 512;
#pragma unroll
        for (int mi = 0; mi < 4; mi++) {
            const int r = m0 + wm * 64 + mi * 16 + lq;
#pragma unroll
            for (int ni = 0; ni < 4; ni++) {
                const int c = n0 + wn * 32 + ni * 8 + 2 * ld;
                *(float2*)(ob + (size_t)r * 512 + c) =
                    make_float2(macc[mi][ni][0] * ds, macc[mi][ni][1] * ds);
                *(float2*)(ob + (size_t)(r + 8) * 512 + c) =
                    make_float2(macc[mi][ni][2] * ds, macc[mi][ni][3] * ds);
            }
        }
    }
}

// ---------------------------------------------------------------------------
// Stage 2: fused bilinear + relu + score, fp16 single x single (1 MMA/k16).
// CTA 128q x 128c; 128-d chunks (2x 64-k chunks); 3-stage pipeline (192KB).
// ---------------------------------------------------------------------------
#define S2_SF 32768                       // halves per stage (A 16K + B 16K)
#define S2_SMEM (3 * S2_SF * 2)           // 196608 B

__global__ void __launch_bounds__(256, 1)
stage2_f16(const __half* __restrict__ q16, const __half* __restrict__ T16,
           const float* __restrict__ score_w, const float* __restrict__ score_b,
           float* __restrict__ other)
{
    extern __shared__ char smc[];
    __half* sm = (__half*)smc;
    const int tid = threadIdx.x;
    const int lane = tid & 31;
    const int wid = tid >> 5;
    const int wm = wid >> 2;
    const int wn = wid & 3;
    const int q0 = blockIdx.y * 128;
    const int c0 = blockIdx.x * 128;

    const size_t aBase = (size_t)(q0 >> 7) * 8 * 8192;
    const size_t bBase = (size_t)(c0 >> 7) * 8 * 8192;

    float sacc[4][4][4];
#pragma unroll
    for (int mi = 0; mi < 4; mi++)
#pragma unroll
        for (int ni = 0; ni < 4; ni++)
#pragma unroll
            for (int r = 0; r < 4; r++) sacc[mi][ni][r] = 0.0f;

    // it = k*4 + t (t: 128-d chunk within slab)
    auto issue = [&](int it, int s) {
        const int k = it >> 2, t = it & 3;
        const __half* srcA = q16 + aBase + (size_t)t * 16384 + tid * 8;
        const __half* srcB = T16 + (size_t)k * 2097152 + bBase + (size_t)t * 16384 + tid * 8;
        uint32_t da = smem_u32(sm + s * S2_SF) + tid * 16;
        uint32_t db = da + 32768;
#pragma unroll
        for (int i = 0; i < 8; i++) {
            asm volatile("cp.async.cg.shared.global [%0], [%1], 16;"
                         :: "r"(da + i * 4096), "l"(srcA + i * 2048));
            asm volatile("cp.async.cg.shared.global [%0], [%1], 16;"
                         :: "r"(db + i * 4096), "l"(srcB + i * 2048));
        }
        asm volatile("cp.async.commit_group;" ::: "memory");
    };

    issue(0, 0);
    issue(1, 1);

    float macc[4][4][4];
    int s = 0;
#pragma unroll 1
    for (int it = 0; it < 32; it++) {
        const int k = it >> 2, t = it & 3;
        if (t == 0) {
#pragma unroll
            for (int mi = 0; mi < 4; mi++)
#pragma unroll
                for (int ni = 0; ni < 4; ni++)
#pragma unroll
                    for (int r = 0; r < 4; r++) macc[mi][ni][r] = 0.0f;
        }

        if (it < 31) asm volatile("cp.async.wait_group 1;" ::: "memory");
        else         asm volatile("cp.async.wait_group 0;" ::: "memory");
        __syncthreads();
        if (it + 2 < 32) {
            int s2 = s + 2; if (s2 >= 3) s2 -= 3;
            issue(it + 2, s2);
        }

        const __half* pa = sm + s * S2_SF;
        const __half* pb = pa + 16384;
#pragma unroll
        for (int kk = 0; kk < 8; kk++) {
            const int sub = (kk >> 2) * 8192;
            const int kf = kk & 3;
            uint4 a[4];
            uint2 b[4];
#pragma unroll
            for (int mi = 0; mi < 4; mi++)
                a[mi] = *(const uint4*)(pa + sub + (((wm * 4 + mi) * 4 + kf) << 8) + lane * 8);
#pragma unroll
            for (int ni = 0; ni < 4; ni++)
                b[ni] = *(const uint2*)(pb + sub + (((wn * 4 + ni) * 4 + kf) << 7) + lane * 4);
#pragma unroll
            for (int mi = 0; mi < 4; mi++)
#pragma unroll
                for (int ni = 0; ni < 4; ni++)
                    mma_f16(macc[mi][ni], (const uint32_t*)&a[mi], (const uint32_t*)&b[ni]);
        }

        if (t == 3) {
            // acc = P * 2^16 (q x2^8, T x2^8): fold 2^-16 into w
            const float w = __ldg(score_w + k) * 1.52587890625e-05f;
#pragma unroll
            for (int mi = 0; mi < 4; mi++)
#pragma unroll
                for (int ni = 0; ni < 4; ni++)
#pragma unroll
                    for (int r = 0; r < 4; r++)
                        sacc[mi][ni][r] = fmaf(fmaxf(macc[mi][ni][r], 0.0f), w,
                                               sacc[mi][ni][r]);
        }
        if (++s >= 3) s -= 3;
    }

    const int lq = lane >> 2;
    const int ld = lane & 3;
    const float sb = __ldg(score_b);
#pragma unroll
    for (int mi = 0; mi < 4; mi++) {
        const int q = q0 + wm * 64 + mi * 16 + lq;
#pragma unroll
        for (int ni = 0; ni < 4; ni++) {
            const int c = c0 + wn * 32 + ni * 8 + 2 * ld;
            *(float2*)(other + (size_t)q * 4096 + c) =
                make_float2(sb + sacc[mi][ni][0], sb + sacc[mi][ni][1]);
            *(float2*)(other + (size_t)(q + 8) * 4096 + c) =
                make_float2(sb + sacc[mi][ni][2], sb + sacc[mi][ni][3]);
        }
    }
}

// ---------------------------------------------------------------------------
// Softmax (paired rows q, q+8); writes sc fp16 A-pack (Ktot=4096, x2^6).
// ---------------------------------------------------------------------------
__global__ void softmax_pack2(const float* __restrict__ o, __half* __restrict__ sc)
{
    const int b = blockIdx.x;
    const int qa = ((b >> 3) << 4) | (b & 7);
    const float* p0 = o + (size_t)qa * 4096;
    const float* p1 = p0 + 8 * 4096;
    const int tid = threadIdx.x;

    float v0[16], v1[16];
    float mx0 = -1e30f, mx1 = -1e30f;
#pragma unroll
    for (int i = 0; i < 16; i++) {
        v0[i] = p0[tid + (i << 8)];
        v1[i] = p1[tid + (i << 8)];
        mx0 = fmaxf(mx0, v0[i]);
        mx1 = fmaxf(mx1, v1[i]);
    }
    __shared__ float sm0[8], sm1[8];
#pragma unroll
    for (int o2 = 16; o2 > 0; o2 >>= 1) {
        mx0 = fmaxf(mx0, __shfl_xor_sync(0xffffffffu, mx0, o2));
        mx1 = fmaxf(mx1, __shfl_xor_sync(0xffffffffu, mx1, o2));
    }
    if ((tid & 31) == 0) { sm0[tid >> 5] = mx0; sm1[tid >> 5] = mx1; }
    __syncthreads();
    mx0 = sm0[0]; mx1 = sm1[0];
#pragma unroll
    for (int i = 1; i < 8; i++) { mx0 = fmaxf(mx0, sm0[i]); mx1 = fmaxf(mx1, sm1[i]); }
    __syncthreads();

    float s0 = 0.0f, s1 = 0.0f;
#pragma unroll
    for (int i = 0; i < 16; i++) {
        v0[i] = expf(v0[i] - mx0); s0 += v0[i];
        v1[i] = expf(v1[i] - mx1); s1 += v1[i];
    }
#pragma unroll
    for (int o2 = 16; o2 > 0; o2 >>= 1) {
        s0 += __shfl_xor_sync(0xffffffffu, s0, o2);
        s1 += __shfl_xor_sync(0xffffffffu, s1, o2);
    }
    if ((tid & 31) == 0) { sm0[tid >> 5] = s0; sm1[tid >> 5] = s1; }
    __syncthreads();
    s0 = 0.0f; s1 = 0.0f;
#pragma unroll
    for (int i = 0; i < 8; i++) { s0 += sm0[i]; s1 += sm1[i]; }
    const float i0 = 64.0f / s0, i1 = 64.0f / s1;   // fold x2^6 scale

#pragma unroll
    for (int i = 0; i < 16; i++) {
        int c = tid + (i << 8);
        size_t off = apack16(qa, c, 4096);
        sc[off] = __float2half_rn(v0[i] * i0);
        sc[off + 2] = __float2half_rn(v1[i] * i1);    // row qa+8: mbit3 -> +2
    }
}

// ---------------------------------------------------------------------------
// Fused stage 5: qf = query + sum_z qfp[z] (smem), out = tanh(qf @ hwT + b).
// ---------------------------------------------------------------------------
__global__ void __launch_bounds__(256, 2)
stage5_fused(const float* __restrict__ query, const float* __restrict__ qfp,
             const float* __restrict__ hwT, const float* __restrict__ hash_b,
             float* __restrict__ out)
{
    __shared__ float qf_s[16 * 512];
    const int tid = threadIdx.x;
    const int qbase = blockIdx.x * 16;
    const size_t S = (size_t)4096 * 512;
    const size_t gbase = (size_t)qbase * 512;

#pragma unroll
    for (int j = 0; j < 8; j++) {
        int i4 = tid + j * 256;
        size_t g = gbase + (size_t)i4 * 4;
        float4 acc = *(const float4*)(query + g);
#pragma unroll
        for (int z = 0; z < 8; z++) {
            float4 p = *(const float4*)(qfp + z * S + g);
            acc.x += p.x; acc.y += p.y; acc.z += p.z; acc.w += p.w;
        }
        *(float4*)(qf_s + i4 * 4) = acc;
    }
    __syncthreads();

    const int q = tid >> 4;
    const int lb = (tid & 15) * 4;
    float a0 = 0, a1 = 0, a2 = 0, a3 = 0;
    const float* qr = qf_s + q * 512;
#pragma unroll 4
    for (int d = 0; d < 512; d += 4) {
        float4 qv = *(const float4*)(qr + d);
        float4 h0 = __ldg((const float4*)(hwT + (size_t)d * 64 + lb));
        float4 h1 = __ldg((const float4*)(hwT + (size_t)(d + 1) * 64 + lb));
        float4 h2 = __ldg((const float4*)(hwT + (size_t)(d + 2) * 64 + lb));
        float4 h3 = __ldg((const float4*)(hwT + (size_t)(d + 3) * 64 + lb));
        a0 = fmaf(qv.x, h0.x, fmaf(qv.y, h1.x, fmaf(qv.z, h2.x, fmaf(qv.w, h3.x, a0))));
        a1 = fmaf(qv.x, h0.y, fmaf(qv.y, h1.y, fmaf(qv.z, h2.y, fmaf(qv.w, h3.y, a1))));
        a2 = fmaf(qv.x, h0.z, fmaf(qv.y, h1.z, fmaf(qv.z, h2.z, fmaf(qv.w, h3.z, a2))));
        a3 = fmaf(qv.x, h0.w, fmaf(qv.y, h1.w, fmaf(qv.z, h2.w, fmaf(qv.w, h3.w, a3))));
    }
    float4 hb = __ldg((const float4*)(hash_b + lb));
    float4 r = make_float4(tanhf(a0 + hb.x), tanhf(a1 + hb.y),
                           tanhf(a2 + hb.z), tanhf(a3 + hb.w));
    *(float4*)(out + (size_t)(qbase + q) * 64 + lb) = r;
}

// ---------------------------------------------------------------------------
// Prep kernels
// ---------------------------------------------------------------------------
__global__ void transpose_hw(const float* __restrict__ hw)
{
    int idx = blockIdx.x * blockDim.x + threadIdx.x;
    int l = idx >> 9;
    int d = idx & 511;
    g_hwT[d * 64 + l] = hw[idx];
}

// invert apack16 for Ktot=512: (m,k) from linear half index
__device__ __forceinline__ void apack16_inv512(int idx, int& m, int& k)
{
    int chunk = idx >> 13;
    int mblk = chunk >> 3, kc = chunk & 7;
    int f = (idx >> 8) & 31;
    int P = idx & 255;
    int g = P >> 5, t = (P >> 3) & 3, kb3 = (P >> 2) & 1, mb3 = (P >> 1) & 1, h = P & 1;
    m = mblk * 128 + (f >> 2) * 16 + mb3 * 8 + g;
    k = kc * 64 + (f & 3) * 16 + kb3 * 8 + t * 2 + h;
}

// query -> A-pack fp16 x2^8
__global__ void pack_q16(const float* __restrict__ q)
{
    int idx = blockIdx.x * blockDim.x + threadIdx.x;   // 0..2097151
    int m, k;
    apack16_inv512(idx, m, k);
    g_q16[idx] = __float2half_rn(q[(size_t)m * 512 + k] * 256.0f);
}

// class -> A-pack fp16 hi/lo x2^8
__global__ void pack_classA16(const float* __restrict__ cv)
{
    int idx = blockIdx.x * blockDim.x + threadIdx.x;
    int m, k;
    apack16_inv512(idx, m, k);
    float v = cv[(size_t)m * 512 + k] * 256.0f;
    __half hi = __float2half_rn(v);
    g_cah[idx] = hi;
    g_cal[idx] = __float2half_rn(v - __half2float(hi));
}

// in [R][C] (R=k-dim, C=n-dim) -> B-pack fp16 hi/lo, one thread per 16-k group.
// within-group half order j=t*4+kb3*2+h <- k=kb3*8+t*2+h
__global__ void pack_B16_split(const float* __restrict__ in,
                               __half* __restrict__ ohi, __half* __restrict__ olo,
                               int R, int C, float scale)
{
    unsigned tt = blockIdx.x * blockDim.x + threadIdx.x;  // C * R/16 threads
    unsigned k16 = tt / (unsigned)C;
    unsigned n = tt - k16 * (unsigned)C;
    int kb = (int)k16 * 16;

    unsigned short h[16], l[16];
#pragma unroll
    for (int i = 0; i < 16; i++) {
        float v = in[(size_t)(kb + i) * C + n] * scale;
        __half hv = __float2half_rn(v);
        h[i] = __half_as_ushort(hv);
        l[i] = __half_as_ushort(__float2half_rn(v - __half2float(hv)));
    }
    size_t base = bpack16((int)n, kb, R);   // 16-half aligned
    const int map[16] = {0,1,8,9,2,3,10,11,4,5,12,13,6,7,14,15};
    uint32_t uh[8], ul[8];
#pragma unroll
    for (int j = 0; j < 8; j++) {
        uh[j] = (uint32_t)h[map[2*j]] | ((uint32_t)h[map[2*j+1]] << 16);
        ul[j] = (uint32_t)l[map[2*j]] | ((uint32_t)l[map[2*j+1]] << 16);
    }
    *(uint4*)(ohi + base)     = make_uint4(uh[0], uh[1], uh[2], uh[3]);
    *(uint4*)(ohi + base + 8) = make_uint4(uh[4], uh[5], uh[6], uh[7]);
    *(uint4*)(olo + base)     = make_uint4(ul[0], ul[1], ul[2], ul[3]);
    *(uint4*)(olo + base + 8) = make_uint4(ul[4], ul[5], ul[6], ul[7]);
}

// class^T -> B-pack fp16 single x2^8 (N=512 d-dim, K=4096 c-dim)
__global__ void pack_classB16(const float* __restrict__ cv)
{
    unsigned tt = blockIdx.x * blockDim.x + threadIdx.x;  // 512 * 256 threads
    unsigned c16 = tt / 512u;
    unsigned d = tt - c16 * 512u;
    int cb = (int)c16 * 16;

    unsigned short h[16];
#pragma unroll
    for (int i = 0; i < 16; i++)
        h[i] = __half_as_ushort(__float2half_rn(cv[(size_t)(cb + i) * 512 + d] * 256.0f));
    size_t base = bpack16((int)d, cb, 4096);
    const int map[16] = {0,1,8,9,2,3,10,11,4,5,12,13,6,7,14,15};
    uint32_t u[8];
#pragma unroll
    for (int j = 0; j < 8; j++)
        u[j] = (uint32_t)h[map[2*j]] | ((uint32_t)h[map[2*j+1]] << 16);
    *(uint4*)(g_cbh + base)     = make_uint4(u[0], u[1], u[2], u[3]);
    *(uint4*)(g_cbh + base + 8) = make_uint4(u[4], u[5], u[6], u[7]);
}

// ---------------------------------------------------------------------------
extern "C" void kernel_launch(void* const* d_in, const int* in_sizes, int n_in,
                              void* d_out, int out_size)
{
    const float* class_v = (const float*)d_in[0];
    const float* query_v = (const float*)d_in[1];
    const float* Mmat    = (const float*)d_in[2];
    const float* score_w = (const float*)d_in[3];
    const float* score_b = (const float*)d_in[4];
    const float* hash_w  = (const float*)d_in[5];
    const float* hash_b  = (const float*)d_in[6];
    float* out = (float*)d_out;

    float *other, *qfp, *hwT;
    __half *T16, *sc16, *q16, *cah, *cal, *mbh, *mbl, *cbh;
    cudaGetSymbolAddress((void**)&T16, g_T16);
    cudaGetSymbolAddress((void**)&other, g_other);
    cudaGetSymbolAddress((void**)&sc16, g_sc16);
    cudaGetSymbolAddress((void**)&q16, g_q16);
    cudaGetSymbolAddress((void**)&cah, g_cah);
    cudaGetSymbolAddress((void**)&cal, g_cal);
    cudaGetSymbolAddress((void**)&mbh, g_mbh);
    cudaGetSymbolAddress((void**)&mbl, g_mbl);
    cudaGetSymbolAddress((void**)&cbh, g_cbh);
    cudaGetSymbolAddress((void**)&qfp, g_qfp);
    cudaGetSymbolAddress((void**)&hwT, g_hwT);

    cudaFuncSetAttribute(stage2_f16, cudaFuncAttributeMaxDynamicSharedMemorySize, S2_SMEM);
    cudaFuncSetAttribute(gemm_f16<1, 0>, cudaFuncAttributeMaxDynamicSharedMemorySize,
                         3 * 4 * 8192 * 2);
    cudaFuncSetAttribute(gemm_f16<0, 1>, cudaFuncAttributeMaxDynamicSharedMemorySize,
                         3 * 2 * 8192 * 2);

    // prep (ordered so stage2 lands near ncu's capture slot)
    pack_q16<<<8192, 256>>>(query_v);
    pack_classA16<<<8192, 256>>>(class_v);
    pack_B16_split<<<512, 256>>>(Mmat, mbh, mbl, 512, 4096, 1024.0f);  // M x2^10

    // Stage 1: T = class @ M  (fp16 3-MMA split, scatter to B-pack)
    gemm_f16<1, 0><<<dim3(32, 32, 1), 256, 3 * 4 * 8192 * 2>>>(
        cah, cal, mbh, mbl, nullptr, T16, 512, 512);

    pack_classB16<<<512, 256>>>(class_v);

    // Stage 2: fused bilinear + relu + score (fp16, 1 MMA/k16)
    stage2_f16<<<dim3(32, 32), 256, S2_SMEM>>>(q16, T16, score_w, score_b, other);

    // Stage 3: softmax -> fp16 packed scores
    softmax_pack2<<<2048, 256>>>(other, sc16);

    // Stage 4: qf partials = sc @ class (fp16 single, split-K=8)
    gemm_f16<0, 1><<<dim3(4, 32, 8), 256, 3 * 2 * 8192 * 2>>>(
        sc16, nullptr, cbh, nullptr, qfp, nullptr, 4096, 512);

    transpose_hw<<<128, 256>>>(hash_w);

    // Stage 5 (fused reduce + residual + tanh GEMM)
    stage5_fused<<<256, 256>>>(query_v, qfp, hwT, hash_b, out);
}